// round 2
// baseline (speedup 1.0000x reference)
#include <cuda_runtime.h>
#include <cuda_bf16.h>
#include <math.h>

// Problem dims
#define BB 256
#define LL 128
#define DD 1024
#define HH 512
#define G4H 2048   // 4*H
#define GNF 4096   // fused gate dim (fwd 2048 | bwd 2048)

// ---------------- scratch (device globals) ----------------------------------
__device__ float g_G[(size_t)LL * BB * GNF];        // [(t*B + b)*4096 + c]  pre-activations (natural t order, both dirs)
__device__ float g_outd[2][(size_t)BB * LL * HH];   // [dir][(b*L + t)*H + j]
__device__ float g_h[2][2][(size_t)BB * HH];
__device__ float g_c[2][2][(size_t)BB * HH];

// ---------------- f32x2 helpers ---------------------------------------------
__device__ __forceinline__ unsigned long long pack2(float lo, float hi) {
    unsigned long long r;
    asm("mov.b64 %0, {%1, %2};" : "=l"(r)
        : "r"(__float_as_uint(lo)), "r"(__float_as_uint(hi)));
    return r;
}
__device__ __forceinline__ unsigned long long packdup(float v) { return pack2(v, v); }
__device__ __forceinline__ void ffma2(unsigned long long& d,
                                      unsigned long long a, unsigned long long b) {
    asm("fma.rn.f32x2 %0, %1, %2, %3;" : "=l"(d) : "l"(a), "l"(b), "l"(d));
}
__device__ __forceinline__ float2 unpack2(unsigned long long v) {
    unsigned int lo, hi;
    asm("mov.b64 {%0, %1}, %2;" : "=r"(lo), "=r"(hi) : "l"(v));
    return make_float2(__uint_as_float(lo), __uint_as_float(hi));
}

// ---------------- init ------------------------------------------------------
__global__ void init_hc_kernel() {
    int i = blockIdx.x * blockDim.x + threadIdx.x;
    if (i < BB * HH) {
        g_h[0][0][i] = 0.f; g_h[1][0][i] = 0.f;
        g_c[0][0][i] = 0.f; g_c[1][0][i] = 0.f;
    }
}

// ---------------- fused input-projection GEMM -------------------------------
// G[m, c] = x[b, t, :] . W(c) + bias(c),  m = t*256 + b
//   c <  2048: W_ih_f row c ; c >= 2048: W_ih_b row c-2048
// BM=128, BN=128, BK=16, 256 threads, 8x8 per thread via fma.rn.f32x2.
__global__ __launch_bounds__(256, 2)
void gemm_in_kernel(const float* __restrict__ X,
                    const float* __restrict__ Wf, const float* __restrict__ Wb,
                    const float* __restrict__ bf, const float* __restrict__ bb)
{
    __shared__ __align__(16) float As[2][16][128];
    __shared__ __align__(16) float Bs[2][16][128];

    const int tid   = threadIdx.x;
    const int mTile = blockIdx.y * 128;
    const int nTile = blockIdx.x * 128;

    // global-load mapping: 128 rows x 16 cols, 2 float4 per thread
    const int lRow = tid & 127;
    const int lCol = (tid >> 7) * 8;   // 0 or 8

    // A row: m = mTile + lRow  ->  x[b, t, :]
    const int m = mTile + lRow;
    const int t = m >> 8;
    const int b = m & 255;
    const float* __restrict__ arow = X + ((size_t)b * LL + t) * DD + lCol;

    // B row: per-tile single weight matrix (2048 % 128 == 0)
    const float* __restrict__ Wsel = (nTile < G4H) ? Wf : Wb;
    const float* __restrict__ bsel = (nTile < G4H) ? bf : bb;
    const int coff = (nTile < G4H) ? nTile : (nTile - G4H);
    const float* __restrict__ brow = Wsel + (size_t)(coff + lRow) * DD + lCol;

    // compute mapping
    const int tr = tid >> 4;   // 0..15 -> rows tr*8..+7
    const int tc = tid & 15;   // 0..15 -> cols tc*8..+7

    unsigned long long acc[8][4];
#pragma unroll
    for (int i = 0; i < 8; i++)
#pragma unroll
        for (int j = 0; j < 4; j++) acc[i][j] = 0ull;

    // preload tile 0
    float4 pa0 = *(const float4*)(arow);
    float4 pa1 = *(const float4*)(arow + 4);
    float4 pb0 = *(const float4*)(brow);
    float4 pb1 = *(const float4*)(brow + 4);
    {
        As[0][lCol + 0][lRow] = pa0.x; As[0][lCol + 1][lRow] = pa0.y;
        As[0][lCol + 2][lRow] = pa0.z; As[0][lCol + 3][lRow] = pa0.w;
        As[0][lCol + 4][lRow] = pa1.x; As[0][lCol + 5][lRow] = pa1.y;
        As[0][lCol + 6][lRow] = pa1.z; As[0][lCol + 7][lRow] = pa1.w;
        Bs[0][lCol + 0][lRow] = pb0.x; Bs[0][lCol + 1][lRow] = pb0.y;
        Bs[0][lCol + 2][lRow] = pb0.z; Bs[0][lCol + 3][lRow] = pb0.w;
        Bs[0][lCol + 4][lRow] = pb1.x; Bs[0][lCol + 5][lRow] = pb1.y;
        Bs[0][lCol + 6][lRow] = pb1.z; Bs[0][lCol + 7][lRow] = pb1.w;
    }
    __syncthreads();

    int buf = 0;
    for (int kt = 0; kt < DD / 16; kt++) {
        if (kt < DD / 16 - 1) {
            const int k0 = (kt + 1) * 16;
            pa0 = *(const float4*)(arow + k0);
            pa1 = *(const float4*)(arow + k0 + 4);
            pb0 = *(const float4*)(brow + k0);
            pb1 = *(const float4*)(brow + k0 + 4);
        }
#pragma unroll
        for (int k = 0; k < 16; k++) {
            float4 a0 = *(const float4*)&As[buf][k][tr * 8];
            float4 a1 = *(const float4*)&As[buf][k][tr * 8 + 4];
            unsigned long long ad[8];
            ad[0] = packdup(a0.x); ad[1] = packdup(a0.y);
            ad[2] = packdup(a0.z); ad[3] = packdup(a0.w);
            ad[4] = packdup(a1.x); ad[5] = packdup(a1.y);
            ad[6] = packdup(a1.z); ad[7] = packdup(a1.w);
            ulonglong2 bv0 = *(const ulonglong2*)&Bs[buf][k][tc * 8];
            ulonglong2 bv1 = *(const ulonglong2*)&Bs[buf][k][tc * 8 + 4];
#pragma unroll
            for (int i = 0; i < 8; i++) {
                ffma2(acc[i][0], ad[i], bv0.x);
                ffma2(acc[i][1], ad[i], bv0.y);
                ffma2(acc[i][2], ad[i], bv1.x);
                ffma2(acc[i][3], ad[i], bv1.y);
            }
        }
        if (kt < DD / 16 - 1) {
            const int nb = buf ^ 1;
            As[nb][lCol + 0][lRow] = pa0.x; As[nb][lCol + 1][lRow] = pa0.y;
            As[nb][lCol + 2][lRow] = pa0.z; As[nb][lCol + 3][lRow] = pa0.w;
            As[nb][lCol + 4][lRow] = pa1.x; As[nb][lCol + 5][lRow] = pa1.y;
            As[nb][lCol + 6][lRow] = pa1.z; As[nb][lCol + 7][lRow] = pa1.w;
            Bs[nb][lCol + 0][lRow] = pb0.x; Bs[nb][lCol + 1][lRow] = pb0.y;
            Bs[nb][lCol + 2][lRow] = pb0.z; Bs[nb][lCol + 3][lRow] = pb0.w;
            Bs[nb][lCol + 4][lRow] = pb1.x; Bs[nb][lCol + 5][lRow] = pb1.y;
            Bs[nb][lCol + 6][lRow] = pb1.z; Bs[nb][lCol + 7][lRow] = pb1.w;
            __syncthreads();
            buf = nb;
        }
    }

    // epilogue
    const float* __restrict__ bptr = bsel + coff + tc * 8;
    float bias8[8];
#pragma unroll
    for (int j = 0; j < 8; j++) bias8[j] = bptr[j];
    const int cBase = nTile + tc * 8;
#pragma unroll
    for (int i = 0; i < 8; i++) {
        const size_t mm = (size_t)(mTile + tr * 8 + i);
        float2 v0 = unpack2(acc[i][0]);
        float2 v1 = unpack2(acc[i][1]);
        float2 v2 = unpack2(acc[i][2]);
        float2 v3 = unpack2(acc[i][3]);
        float4 o0 = make_float4(v0.x + bias8[0], v0.y + bias8[1],
                                v1.x + bias8[2], v1.y + bias8[3]);
        float4 o1 = make_float4(v2.x + bias8[4], v2.y + bias8[5],
                                v3.x + bias8[6], v3.y + bias8[7]);
        *(float4*)&g_G[mm * GNF + cBase]     = o0;
        *(float4*)&g_G[mm * GNF + cBase + 4] = o1;
    }
}

// ---------------- recurrent step --------------------------------------------
// Per dir: C[b, c] = h[b,:].Whh_row(c), c gate-interleaved: c -> gate=c&3, j=c>>2
// BM=64 (batch), BN=128 (cols), BK=16, 256 threads, 4x8 per thread (fma2).
// grid (16, 4, 2) = 128 blocks.
__global__ __launch_bounds__(256)
void lstm_step_kernel(const int* __restrict__ x_len,
                      const float* __restrict__ W_hh_f,
                      const float* __restrict__ W_hh_b,
                      int t)
{
    __shared__ __align__(16) float Hs[2][16][64];
    __shared__ __align__(16) float Ws[2][16][128];

    const int cTile = blockIdx.x * 128;
    const int b0    = blockIdx.y * 64;
    const int dir   = blockIdx.z;

    const float* __restrict__ W = dir ? W_hh_b : W_hh_f;
    float* __restrict__ outp    = g_outd[dir];
    const int p = t & 1;
    const float* __restrict__ hprev = g_h[dir][p];
    float* __restrict__ hnext       = g_h[dir][p ^ 1];
    const float* __restrict__ cprev = g_c[dir][p];
    float* __restrict__ cnext       = g_c[dir][p ^ 1];

    const int tid = threadIdx.x;

    // load mappings
    const int hRow = tid & 63;
    const int hCol = (tid >> 6) * 4;          // 0,4,8,12
    const float* __restrict__ hrow = hprev + (size_t)(b0 + hRow) * HH + hCol;

    const int wRow = tid & 127;
    const int wCol = (tid >> 7) * 8;          // 0 or 8
    const int c_ld = cTile + wRow;
    const int wr   = (c_ld & 3) * HH + (c_ld >> 2);  // gate-interleaved W row
    const float* __restrict__ wrow = W + (size_t)wr * HH + wCol;

    // compute mapping
    const int tm = tid >> 4;   // 0..15 -> batches tm*4..+3
    const int tc = tid & 15;   // 0..15 -> cols tc*8..+7

    unsigned long long acc[4][4];
#pragma unroll
    for (int r = 0; r < 4; r++)
#pragma unroll
        for (int g = 0; g < 4; g++) acc[r][g] = 0ull;

    // preload tile 0
    float4 ph  = *(const float4*)(hrow);
    float4 pw0 = *(const float4*)(wrow);
    float4 pw1 = *(const float4*)(wrow + 4);
    {
        Hs[0][hCol + 0][hRow] = ph.x; Hs[0][hCol + 1][hRow] = ph.y;
        Hs[0][hCol + 2][hRow] = ph.z; Hs[0][hCol + 3][hRow] = ph.w;
        Ws[0][wCol + 0][wRow] = pw0.x; Ws[0][wCol + 1][wRow] = pw0.y;
        Ws[0][wCol + 2][wRow] = pw0.z; Ws[0][wCol + 3][wRow] = pw0.w;
        Ws[0][wCol + 4][wRow] = pw1.x; Ws[0][wCol + 5][wRow] = pw1.y;
        Ws[0][wCol + 6][wRow] = pw1.z; Ws[0][wCol + 7][wRow] = pw1.w;
    }
    __syncthreads();

    int buf = 0;
    for (int kt = 0; kt < HH / 16; kt++) {
        if (kt < HH / 16 - 1) {
            const int k0 = (kt + 1) * 16;
            ph  = *(const float4*)(hrow + k0);
            pw0 = *(const float4*)(wrow + k0);
            pw1 = *(const float4*)(wrow + k0 + 4);
        }
#pragma unroll
        for (int k = 0; k < 16; k++) {
            float4 h4 = *(const float4*)&Hs[buf][k][tm * 4];
            unsigned long long hd[4];
            hd[0] = packdup(h4.x); hd[1] = packdup(h4.y);
            hd[2] = packdup(h4.z); hd[3] = packdup(h4.w);
            ulonglong2 bv0 = *(const ulonglong2*)&Ws[buf][k][tc * 8];
            ulonglong2 bv1 = *(const ulonglong2*)&Ws[buf][k][tc * 8 + 4];
#pragma unroll
            for (int r = 0; r < 4; r++) {
                ffma2(acc[r][0], hd[r], bv0.x);
                ffma2(acc[r][1], hd[r], bv0.y);
                ffma2(acc[r][2], hd[r], bv1.x);
                ffma2(acc[r][3], hd[r], bv1.y);
            }
        }
        if (kt < HH / 16 - 1) {
            const int nb = buf ^ 1;
            Hs[nb][hCol + 0][hRow] = ph.x; Hs[nb][hCol + 1][hRow] = ph.y;
            Hs[nb][hCol + 2][hRow] = ph.z; Hs[nb][hCol + 3][hRow] = ph.w;
            Ws[nb][wCol + 0][wRow] = pw0.x; Ws[nb][wCol + 1][wRow] = pw0.y;
            Ws[nb][wCol + 2][wRow] = pw0.z; Ws[nb][wCol + 3][wRow] = pw0.w;
            Ws[nb][wCol + 4][wRow] = pw1.x; Ws[nb][wCol + 5][wRow] = pw1.y;
            Ws[nb][wCol + 6][wRow] = pw1.z; Ws[nb][wCol + 7][wRow] = pw1.w;
            __syncthreads();
            buf = nb;
        }
    }

    // epilogue: cols tc*8..+7 = j0,j0+1 with 4 gates each
    const int j0 = (cTile >> 2) + tc * 2;
#pragma unroll
    for (int r = 0; r < 4; r++) {
        const int b   = b0 + tm * 4 + r;
        const int len = x_len[b];
        int tq = t;
        if (dir) { tq = len - 1 - t; if (tq < 0) tq = 0; }
        const float* __restrict__ gpre =
            g_G + ((size_t)tq * BB + b) * GNF + dir * G4H;
        const bool valid = (t < len);

        float2 v0 = unpack2(acc[r][0]);   // (i,f) @ j0
        float2 v1 = unpack2(acc[r][1]);   // (g,o) @ j0
        float2 v2 = unpack2(acc[r][2]);   // (i,f) @ j0+1
        float2 v3 = unpack2(acc[r][3]);   // (g,o) @ j0+1

#pragma unroll
        for (int jj = 0; jj < 2; jj++) {
            const int j = j0 + jj;
            float gi = (jj ? v2.x : v0.x) + gpre[j];
            float gf = (jj ? v2.y : v0.y) + gpre[HH + j];
            float gg = (jj ? v3.x : v1.x) + gpre[2 * HH + j];
            float go = (jj ? v3.y : v1.y) + gpre[3 * HH + j];
            float i_ = 1.f / (1.f + expf(-gi));
            float f_ = 1.f / (1.f + expf(-gf));
            float g_ = tanhf(gg);
            float o_ = 1.f / (1.f + expf(-go));
            const size_t hc = (size_t)b * HH + j;
            float cp = cprev[hc];
            float hp = hprev[hc];
            float cn = f_ * cp + i_ * g_;
            float hn = o_ * tanhf(cn);
            hnext[hc] = valid ? hn : hp;
            cnext[hc] = valid ? cn : cp;
            outp[((size_t)b * LL + t) * HH + j] = valid ? hn : 0.f;
        }
    }
}

// ---------------- attention + head (one block per batch) --------------------
__global__ __launch_bounds__(256)
void final_kernel(const float* __restrict__ x, const int* __restrict__ x_len,
                  const float* __restrict__ target_word,
                  const float* __restrict__ W_h, const float* __restrict__ b_tanh,
                  const float* __restrict__ W_lin, const float* __restrict__ b_lin,
                  const float* __restrict__ W_out, const float* __restrict__ b_out,
                  float* __restrict__ out)
{
    __shared__ float s_u[LL];
    __shared__ float s_ctx[2 * HH];
    __shared__ float s_lin[512];
    __shared__ float s_red[8];
    __shared__ float s_twdot;

    const int b    = blockIdx.x;
    const int tid  = threadIdx.x;
    const int warp = tid >> 5;
    const int lane = tid & 31;
    const int len  = x_len[b];

    // 1. target-word dot
    {
        float partial = 0.f;
        for (int d = tid; d < DD; d += 256) {
            float s = 0.f;
#pragma unroll
            for (int k = 0; k < 5; k++)
                s += target_word[((size_t)b * 5 + k) * DD + d];
            partial = fmaf(s * 0.2f, W_h[DD + d], partial);
        }
#pragma unroll
        for (int off = 16; off; off >>= 1)
            partial += __shfl_xor_sync(0xffffffffu, partial, off);
        if (lane == 0) s_red[warp] = partial;
        __syncthreads();
        if (tid == 0) {
            float s = 0.f;
            for (int w = 0; w < 8; w++) s += s_red[w];
            s_twdot = s;
        }
        __syncthreads();
    }
    const float twdot = s_twdot;

    // 2. attention logits
    for (int i = 0; i < 16; i++) {
        const int t = warp * 16 + i;
        const float* xe = x + ((size_t)b * LL + t) * DD;
        float a = 0.f;
#pragma unroll 8
        for (int q = 0; q < 32; q++) {
            int d = lane + q * 32;
            a = fmaf(xe[d], W_h[d], a);
        }
#pragma unroll
        for (int off = 16; off; off >>= 1)
            a += __shfl_xor_sync(0xffffffffu, a, off);
        if (lane == 0)
            s_u[t] = (t < len) ? (a + twdot + b_tanh[t]) : -1e6f;
    }
    __syncthreads();

    // 3. softmax over L
    if (warp == 0) {
        float v[4];
#pragma unroll
        for (int q = 0; q < 4; q++) v[q] = s_u[lane + q * 32];
        float m = fmaxf(fmaxf(v[0], v[1]), fmaxf(v[2], v[3]));
#pragma unroll
        for (int off = 16; off; off >>= 1)
            m = fmaxf(m, __shfl_xor_sync(0xffffffffu, m, off));
        float e[4], s = 0.f;
#pragma unroll
        for (int q = 0; q < 4; q++) { e[q] = expf(v[q] - m); s += e[q]; }
#pragma unroll
        for (int off = 16; off; off >>= 1)
            s += __shfl_xor_sync(0xffffffffu, s, off);
        float inv = 1.f / s;
#pragma unroll
        for (int q = 0; q < 4; q++) s_u[lane + q * 32] = e[q] * inv;
    }
    __syncthreads();

    // 4. context
    {
        float accj[4] = {0.f, 0.f, 0.f, 0.f};
        const float* outf = g_outd[0] + (size_t)b * LL * HH;
        const float* outb = g_outd[1] + (size_t)b * LL * HH;
        for (int t = 0; t < LL; t++) {
            const float a = s_u[t];
            int t2 = len - 1 - t;
            if (t2 < 0) t2 = 0;
#pragma unroll
            for (int q = 0; q < 4; q++) {
                const int j = tid + q * 256;
                float hv;
                if (j < HH) hv = outf[(size_t)t * HH + j];
                else        hv = outb[(size_t)t2 * HH + (j - HH)];
                accj[q] = fmaf(a, hv, accj[q]);
            }
        }
#pragma unroll
        for (int q = 0; q < 4; q++) s_ctx[tid + q * 256] = accj[q];
    }
    __syncthreads();

    // 5. lin = relu(ctx @ W_lin^T + b_lin)
    for (int i = 0; i < 64; i++) {
        const int o = warp * 64 + i;
        const float* wr = W_lin + (size_t)o * (2 * HH);
        float a = 0.f;
#pragma unroll 8
        for (int q = 0; q < 32; q++) {
            int d = lane + q * 32;
            a = fmaf(s_ctx[d], wr[d], a);
        }
#pragma unroll
        for (int off = 16; off; off >>= 1)
            a += __shfl_xor_sync(0xffffffffu, a, off);
        if (lane == 0) s_lin[o] = fmaxf(a + b_lin[o], 0.f);
    }
    __syncthreads();

    // 6. out
    if (warp == 0) {
#pragma unroll
        for (int o = 0; o < 3; o++) {
            const float* wr = W_out + (size_t)o * 512;
            float a = 0.f;
#pragma unroll
            for (int q = 0; q < 16; q++) {
                int d = lane + q * 32;
                a = fmaf(s_lin[d], wr[d], a);
            }
#pragma unroll
            for (int off = 16; off; off >>= 1)
                a += __shfl_xor_sync(0xffffffffu, a, off);
            if (lane == 0) out[b * 3 + o] = a + b_out[o];
        }
    }
}

// ---------------- launch ----------------------------------------------------
extern "C" void kernel_launch(void* const* d_in, const int* in_sizes, int n_in,
                              void* d_out, int out_size)
{
    const float* x           = (const float*)d_in[0];
    const int*   x_len       = (const int*)d_in[1];
    const float* target_word = (const float*)d_in[3];
    const float* W_ih_f      = (const float*)d_in[5];
    const float* W_hh_f      = (const float*)d_in[6];
    const float* b_f         = (const float*)d_in[7];
    const float* W_ih_b      = (const float*)d_in[8];
    const float* W_hh_b      = (const float*)d_in[9];
    const float* b_b         = (const float*)d_in[10];
    const float* W_h         = (const float*)d_in[11];
    const float* b_tanh      = (const float*)d_in[12];
    const float* W_lin       = (const float*)d_in[13];
    const float* b_lin       = (const float*)d_in[14];
    const float* W_out       = (const float*)d_in[15];
    const float* b_out       = (const float*)d_in[16];
    float* out = (float*)d_out;

    init_hc_kernel<<<(BB * HH + 255) / 256, 256>>>();

    dim3 ggrid(GNF / 128, (LL * BB) / 128);   // (32, 256)
    gemm_in_kernel<<<ggrid, 256>>>(x, W_ih_f, W_ih_b, b_f, b_b);

    dim3 sgrid(G4H / 128, BB / 64, 2);        // (16, 4, 2)
    for (int t = 0; t < LL; t++)
        lstm_step_kernel<<<sgrid, 256>>>(x_len, W_hh_f, W_hh_b, t);

    final_kernel<<<BB, 256>>>(x, x_len, target_word, W_h, b_tanh,
                              W_lin, b_lin, W_out, b_out, out);
}

// round 4
// speedup vs baseline: 1.6451x; 1.6451x over previous
#include <cuda_runtime.h>
#include <cuda_bf16.h>
#include <math.h>
#include <stdint.h>

// Problem dims
#define BB 256
#define LL 128
#define DD 1024
#define HH 512
#define G4H 2048   // 4*H
#define GNF 4096   // fused gate dim (fwd 2048 | bwd 2048)
#define KS 3072    // split-K: [hi|lo|hi] x [hi|hi|lo]
#define MM_TOT (LL * BB)   // 32768

// ---------------- scratch (device globals) ----------------------------------
__device__ float g_G[(size_t)MM_TOT * GNF];          // [(t*B+b)*4096 + c]
__device__ float g_outd[2][(size_t)BB * LL * HH];    // [dir][(b*L+t)*H + j]
__device__ float g_h[2][2][(size_t)BB * HH];
__device__ float g_c[2][2][(size_t)BB * HH];
__device__ __nv_bfloat16 g_Xs[(size_t)MM_TOT * KS];  // [m][k'], A' = [Xhi|Xlo|Xhi]
__device__ __nv_bfloat16 g_Ws[(size_t)GNF * KS];     // [n][k'], B' = [Whi|Whi|Wlo]
__device__ float g_bias[GNF];

// ---------------- helpers ----------------------------------------------------
__device__ __forceinline__ uint32_t smem_u32(const void* p) {
    uint32_t a;
    asm("{ .reg .u64 t; cvta.to.shared.u64 t, %1; cvt.u32.u64 %0, t; }"
        : "=r"(a) : "l"(p));
    return a;
}
#define CPA16(dst, src) \
    asm volatile("cp.async.ca.shared.global [%0], [%1], 16;" :: "r"(dst), "l"(src))
#define CPA_COMMIT() asm volatile("cp.async.commit_group;" ::: "memory")

__device__ __forceinline__ void ldmatrix_x4(uint32_t* r, uint32_t addr) {
    asm volatile("ldmatrix.sync.aligned.m8n8.x4.shared.b16 {%0,%1,%2,%3}, [%4];"
                 : "=r"(r[0]), "=r"(r[1]), "=r"(r[2]), "=r"(r[3]) : "r"(addr));
}
__device__ __forceinline__ void mma16816(float* c, const uint32_t* a,
                                         uint32_t b0, uint32_t b1) {
    asm volatile(
        "mma.sync.aligned.m16n8k16.row.col.f32.bf16.bf16.f32 "
        "{%0,%1,%2,%3}, {%4,%5,%6,%7}, {%8,%9}, {%0,%1,%2,%3};"
        : "+f"(c[0]), "+f"(c[1]), "+f"(c[2]), "+f"(c[3])
        : "r"(a[0]), "r"(a[1]), "r"(a[2]), "r"(a[3]), "r"(b0), "r"(b1));
}

// ---------------- init -------------------------------------------------------
__global__ void init_hc_kernel() {
    int i = blockIdx.x * blockDim.x + threadIdx.x;
    if (i < BB * HH) {
        g_h[0][0][i] = 0.f; g_h[1][0][i] = 0.f;
        g_c[0][0][i] = 0.f; g_c[1][0][i] = 0.f;
    }
}

// ---------------- fp32 -> bf16 hi/lo split converters ------------------------
__global__ __launch_bounds__(256)
void convert_x_kernel(const float* __restrict__ X) {
    const int bt = blockIdx.x;            // b*L + t
    const int b = bt >> 7;
    const int t = bt & 127;
    const float4 v = ((const float4*)(X + (size_t)bt * DD))[threadIdx.x];
    __nv_bfloat16 hi4[4], lo4[4];
    hi4[0] = __float2bfloat16_rn(v.x); lo4[0] = __float2bfloat16_rn(v.x - __bfloat162float(hi4[0]));
    hi4[1] = __float2bfloat16_rn(v.y); lo4[1] = __float2bfloat16_rn(v.y - __bfloat162float(hi4[1]));
    hi4[2] = __float2bfloat16_rn(v.z); lo4[2] = __float2bfloat16_rn(v.z - __bfloat162float(hi4[2]));
    hi4[3] = __float2bfloat16_rn(v.w); lo4[3] = __float2bfloat16_rn(v.w - __bfloat162float(hi4[3]));
    const size_t base = ((size_t)t * BB + b) * KS + threadIdx.x * 4;
    *(uint2*)&g_Xs[base]        = *(const uint2*)hi4;   // seg0: Xhi
    *(uint2*)&g_Xs[base + DD]   = *(const uint2*)lo4;   // seg1: Xlo
    *(uint2*)&g_Xs[base + 2*DD] = *(const uint2*)hi4;   // seg2: Xhi
}

__global__ __launch_bounds__(256)
void convert_w_kernel(const float* __restrict__ Wf, const float* __restrict__ Wb,
                      const float* __restrict__ bf, const float* __restrict__ bb) {
    const int n = blockIdx.x;             // 0..4095
    const float* src = (n < G4H) ? (Wf + (size_t)n * DD)
                                 : (Wb + (size_t)(n - G4H) * DD);
    const float4 v = ((const float4*)src)[threadIdx.x];
    __nv_bfloat16 hi4[4], lo4[4];
    hi4[0] = __float2bfloat16_rn(v.x); lo4[0] = __float2bfloat16_rn(v.x - __bfloat162float(hi4[0]));
    hi4[1] = __float2bfloat16_rn(v.y); lo4[1] = __float2bfloat16_rn(v.y - __bfloat162float(hi4[1]));
    hi4[2] = __float2bfloat16_rn(v.z); lo4[2] = __float2bfloat16_rn(v.z - __bfloat162float(hi4[2]));
    hi4[3] = __float2bfloat16_rn(v.w); lo4[3] = __float2bfloat16_rn(v.w - __bfloat162float(hi4[3]));
    const size_t base = (size_t)n * KS + threadIdx.x * 4;
    *(uint2*)&g_Ws[base]        = *(const uint2*)hi4;   // seg0: Whi
    *(uint2*)&g_Ws[base + DD]   = *(const uint2*)hi4;   // seg1: Whi
    *(uint2*)&g_Ws[base + 2*DD] = *(const uint2*)lo4;   // seg2: Wlo
    if (threadIdx.x == 0)
        g_bias[n] = (n < G4H) ? bf[n] : bb[n - G4H];
}

// ---------------- mma.sync input-projection GEMM ----------------------------
// G = A'(32768x3072) @ B'^T(3072x4096) + bias.
// 128x128 block tile, BK=32, 8 warps (4m x 2n), warp tile 32x64.
// smem rows padded to 80B for conflict-free ldmatrix.
#define NKT (KS / 32)      // 96 k-tiles
#define SROW 80            // bytes per smem row (32 bf16 + 16B pad)
#define STILE (128 * SROW) // 10240 B per tile buffer

__global__ __launch_bounds__(256, 2)
void gemm_mma_kernel() {
    __shared__ __align__(16) char smA[2][STILE];
    __shared__ __align__(16) char smB[2][STILE];

    const int tid  = threadIdx.x;
    const int wid  = tid >> 5;
    const int lane = tid & 31;
    const int nTile = blockIdx.x * 128;
    const int mTile = blockIdx.y * 128;

    const int wm = wid & 3;         // 0..3
    const int wn = wid >> 2;        // 0..1
    const int m0 = wm * 32;
    const int n0 = wn * 64;

    // global->shared load mapping: row = tid>>1, 32B half = tid&1
    const int lrow = tid >> 1;
    const int lk   = tid & 1;
    const __nv_bfloat16* __restrict__ gA =
        g_Xs + (size_t)(mTile + lrow) * KS + lk * 16;
    const __nv_bfloat16* __restrict__ gB =
        g_Ws + (size_t)(nTile + lrow) * KS + lk * 16;

    const uint32_t baseA = smem_u32(smA);
    const uint32_t baseB = smem_u32(smB);
    const uint32_t stDstA = baseA + lrow * SROW + lk * 32;
    const uint32_t stDstB = baseB + lrow * SROW + lk * 32;

    float acc[2][8][4];
#pragma unroll
    for (int i = 0; i < 2; i++)
#pragma unroll
        for (int j = 0; j < 8; j++)
#pragma unroll
            for (int q = 0; q < 4; q++) acc[i][j][q] = 0.f;

    // lane decode for ldmatrix
    const int r8 = lane & 7;
    const int tI = lane >> 3;       // tile idx 0..3
    // A: row bit = tI&1, k-half = tI>>1 ; B: row bit = tI>>1, k-half = tI&1
    const uint32_t aLaneOff = (uint32_t)((r8 + (tI & 1) * 8) * SROW + (tI >> 1) * 16);
    const uint32_t bLaneOff = (uint32_t)((r8 + (tI >> 1) * 8) * SROW + (tI & 1) * 16);

    // prologue: tile 0 -> buf 0
    CPA16(stDstA, gA);        CPA16(stDstA + 16, gA + 8);
    CPA16(stDstB, gB);        CPA16(stDstB + 16, gB + 8);
    CPA_COMMIT();

    int buf = 0;
    for (int kt = 0; kt < NKT; kt++) {
        if (kt < NKT - 1) {
            const __nv_bfloat16* pa = gA + (size_t)(kt + 1) * 32;
            const __nv_bfloat16* pb = gB + (size_t)(kt + 1) * 32;
            const uint32_t dA = stDstA + (buf ^ 1) * STILE;
            const uint32_t dB = stDstB + (buf ^ 1) * STILE;
            CPA16(dA, pa); CPA16(dA + 16, pa + 8);
            CPA16(dB, pb); CPA16(dB + 16, pb + 8);
            CPA_COMMIT();
            asm volatile("cp.async.wait_group 1;" ::: "memory");
        } else {
            asm volatile("cp.async.wait_group 0;" ::: "memory");
        }
        __syncthreads();

        const uint32_t abuf = baseA + buf * STILE;
        const uint32_t bbuf = baseB + buf * STILE;
#pragma unroll
        for (int kk = 0; kk < 2; kk++) {
            uint32_t afr[2][4], bfr[4][4];
#pragma unroll
            for (int mi = 0; mi < 2; mi++)
                ldmatrix_x4(afr[mi],
                            abuf + (uint32_t)((m0 + mi * 16) * SROW + kk * 32) + aLaneOff);
#pragma unroll
            for (int nb = 0; nb < 4; nb++)
                ldmatrix_x4(bfr[nb],
                            bbuf + (uint32_t)((n0 + nb * 16) * SROW + kk * 32) + bLaneOff);
#pragma unroll
            for (int mi = 0; mi < 2; mi++)
#pragma unroll
                for (int ni = 0; ni < 8; ni++) {
                    const uint32_t* bp = &bfr[ni >> 1][(ni & 1) * 2];
                    mma16816(acc[mi][ni], afr[mi], bp[0], bp[1]);
                }
        }
        __syncthreads();
        buf ^= 1;
    }

    // epilogue
    const int gid = lane >> 2;
    const int tig = lane & 3;
#pragma unroll
    for (int mi = 0; mi < 2; mi++) {
        const int m = mTile + m0 + mi * 16 + gid;
#pragma unroll
        for (int ni = 0; ni < 8; ni++) {
            const int n = nTile + n0 + ni * 8 + tig * 2;
            const float2 bv = *(const float2*)&g_bias[n];
            float2 o0 = make_float2(acc[mi][ni][0] + bv.x, acc[mi][ni][1] + bv.y);
            float2 o1 = make_float2(acc[mi][ni][2] + bv.x, acc[mi][ni][3] + bv.y);
            *(float2*)&g_G[(size_t)m * GNF + n]       = o0;
            *(float2*)&g_G[(size_t)(m + 8) * GNF + n] = o1;
        }
    }
}

// ---------------- recurrent step (R1-proven tiling) --------------------------
// grid: (H/16=32, B/64=4, 2 dirs), 256 threads.
__global__ __launch_bounds__(256)
void lstm_step_kernel(const int* __restrict__ x_len,
                      const float* __restrict__ W_hh_f,
                      const float* __restrict__ W_hh_b,
                      int t)
{
    __shared__ __align__(16) float Hs[16][68];
    __shared__ __align__(16) float Ws[16][68];

    const int j0  = blockIdx.x * 16;
    const int b0  = blockIdx.y * 64;
    const int dir = blockIdx.z;

    const float* __restrict__ W = dir ? W_hh_b : W_hh_f;
    float* __restrict__ outp    = g_outd[dir];
    const int p = t & 1;
    const float* __restrict__ hprev = g_h[dir][p];
    float* __restrict__ hnext       = g_h[dir][p ^ 1];
    const float* __restrict__ cprev = g_c[dir][p];
    float* __restrict__ cnext       = g_c[dir][p ^ 1];

    const int tid = threadIdx.x;
    const int ty = tid >> 4;
    const int tx = tid & 15;

    const int lr = tid >> 2;
    const int lc = (tid & 3) * 4;
    const int n_ld = (lr & 3) * HH + j0 + (lr >> 2);
    const float* __restrict__ wrow = W + (size_t)n_ld * HH;
    const float* __restrict__ hrow = hprev + (size_t)(b0 + lr) * HH;

    float acc[4][4];
#pragma unroll
    for (int r = 0; r < 4; r++)
#pragma unroll
        for (int g = 0; g < 4; g++) acc[r][g] = 0.f;

    for (int k0 = 0; k0 < HH; k0 += 16) {
        float4 hv = *(const float4*)(hrow + k0 + lc);
        float4 wv = *(const float4*)(wrow + k0 + lc);
        Hs[lc + 0][lr] = hv.x; Hs[lc + 1][lr] = hv.y;
        Hs[lc + 2][lr] = hv.z; Hs[lc + 3][lr] = hv.w;
        Ws[lc + 0][lr] = wv.x; Ws[lc + 1][lr] = wv.y;
        Ws[lc + 2][lr] = wv.z; Ws[lc + 3][lr] = wv.w;
        __syncthreads();
#pragma unroll
        for (int k = 0; k < 16; k++) {
            float4 hh = *(const float4*)&Hs[k][ty * 4];
            float4 ww = *(const float4*)&Ws[k][tx * 4];
            float hr[4] = {hh.x, hh.y, hh.z, hh.w};
            float wr[4] = {ww.x, ww.y, ww.z, ww.w};
#pragma unroll
            for (int r = 0; r < 4; r++)
#pragma unroll
                for (int g = 0; g < 4; g++)
                    acc[r][g] = fmaf(hr[r], wr[g], acc[r][g]);
        }
        __syncthreads();
    }

    const int j = j0 + tx;
#pragma unroll
    for (int r = 0; r < 4; r++) {
        const int b = b0 + ty * 4 + r;
        const int len = x_len[b];
        int tq = t;
        if (dir) { tq = len - 1 - t; if (tq < 0) tq = 0; }
        const float* gpre = g_G + ((size_t)tq * BB + b) * GNF + dir * G4H;
        float gi = acc[r][0] + gpre[0 * HH + j];
        float gf = acc[r][1] + gpre[1 * HH + j];
        float gg = acc[r][2] + gpre[2 * HH + j];
        float go = acc[r][3] + gpre[3 * HH + j];
        float i_ = 1.f / (1.f + expf(-gi));
        float f_ = 1.f / (1.f + expf(-gf));
        float g_ = tanhf(gg);
        float o_ = 1.f / (1.f + expf(-go));
        const size_t hc = (size_t)b * HH + j;
        float cp = cprev[hc];
        float hp = hprev[hc];
        float cn = f_ * cp + i_ * g_;
        float hn = o_ * tanhf(cn);
        bool valid = (t < len);
        hnext[hc] = valid ? hn : hp;
        cnext[hc] = valid ? cn : cp;
        outp[((size_t)b * LL + t) * HH + j] = valid ? hn : 0.f;
    }
}

// ---------------- attention + head (one block per batch) ---------------------
__global__ __launch_bounds__(256)
void final_kernel(const float* __restrict__ x, const int* __restrict__ x_len,
                  const float* __restrict__ target_word,
                  const float* __restrict__ W_h, const float* __restrict__ b_tanh,
                  const float* __restrict__ W_lin, const float* __restrict__ b_lin,
                  const float* __restrict__ W_out, const float* __restrict__ b_out,
                  float* __restrict__ out)
{
    __shared__ float s_u[LL];
    __shared__ float s_ctx[2 * HH];
    __shared__ float s_lin[512];
    __shared__ float s_red[8];
    __shared__ float s_twdot;

    const int b    = blockIdx.x;
    const int tid  = threadIdx.x;
    const int warp = tid >> 5;
    const int lane = tid & 31;
    const int len  = x_len[b];

    {
        float partial = 0.f;
        for (int d = tid; d < DD; d += 256) {
            float s = 0.f;
#pragma unroll
            for (int k = 0; k < 5; k++)
                s += target_word[((size_t)b * 5 + k) * DD + d];
            partial = fmaf(s * 0.2f, W_h[DD + d], partial);
        }
#pragma unroll
        for (int off = 16; off; off >>= 1)
            partial += __shfl_xor_sync(0xffffffffu, partial, off);
        if (lane == 0) s_red[warp] = partial;
        __syncthreads();
        if (tid == 0) {
            float s = 0.f;
            for (int w = 0; w < 8; w++) s += s_red[w];
            s_twdot = s;
        }
        __syncthreads();
    }
    const float twdot = s_twdot;

    for (int i = 0; i < 16; i++) {
        const int t = warp * 16 + i;
        const float* xe = x + ((size_t)b * LL + t) * DD;
        float a = 0.f;
#pragma unroll 8
        for (int q = 0; q < 32; q++) {
            int d = lane + q * 32;
            a = fmaf(xe[d], W_h[d], a);
        }
#pragma unroll
        for (int off = 16; off; off >>= 1)
            a += __shfl_xor_sync(0xffffffffu, a, off);
        if (lane == 0)
            s_u[t] = (t < len) ? (a + twdot + b_tanh[t]) : -1e6f;
    }
    __syncthreads();

    if (warp == 0) {
        float v[4];
#pragma unroll
        for (int q = 0; q < 4; q++) v[q] = s_u[lane + q * 32];
        float m = fmaxf(fmaxf(v[0], v[1]), fmaxf(v[2], v[3]));
#pragma unroll
        for (int off = 16; off; off >>= 1)
            m = fmaxf(m, __shfl_xor_sync(0xffffffffu, m, off));
        float e[4], s = 0.f;
#pragma unroll
        for (int q = 0; q < 4; q++) { e[q] = expf(v[q] - m); s += e[q]; }
#pragma unroll
        for (int off = 16; off; off >>= 1)
            s += __shfl_xor_sync(0xffffffffu, s, off);
        float inv = 1.f / s;
#pragma unroll
        for (int q = 0; q < 4; q++) s_u[lane + q * 32] = e[q] * inv;
    }
    __syncthreads();

    {
        float accj[4] = {0.f, 0.f, 0.f, 0.f};
        const float* outf = g_outd[0] + (size_t)b * LL * HH;
        const float* outb = g_outd[1] + (size_t)b * LL * HH;
        for (int t = 0; t < LL; t++) {
            const float a = s_u[t];
            int t2 = len - 1 - t;
            if (t2 < 0) t2 = 0;
#pragma unroll
            for (int q = 0; q < 4; q++) {
                const int j = tid + q * 256;
                float hv;
                if (j < HH) hv = outf[(size_t)t * HH + j];
                else        hv = outb[(size_t)t2 * HH + (j - HH)];
                accj[q] = fmaf(a, hv, accj[q]);
            }
        }
#pragma unroll
        for (int q = 0; q < 4; q++) s_ctx[tid + q * 256] = accj[q];
    }
    __syncthreads();

    for (int i = 0; i < 64; i++) {
        const int o = warp * 64 + i;
        const float* wr = W_lin + (size_t)o * (2 * HH);
        float a = 0.f;
#pragma unroll 8
        for (int q = 0; q < 32; q++) {
            int d = lane + q * 32;
            a = fmaf(s_ctx[d], wr[d], a);
        }
#pragma unroll
        for (int off = 16; off; off >>= 1)
            a += __shfl_xor_sync(0xffffffffu, a, off);
        if (lane == 0) s_lin[o] = fmaxf(a + b_lin[o], 0.f);
    }
    __syncthreads();

    if (warp == 0) {
#pragma unroll
        for (int o = 0; o < 3; o++) {
            const float* wr = W_out + (size_t)o * 512;
            float a = 0.f;
#pragma unroll
            for (int q = 0; q < 16; q++) {
                int d = lane + q * 32;
                a = fmaf(s_lin[d], wr[d], a);
            }
#pragma unroll
            for (int off = 16; off; off >>= 1)
                a += __shfl_xor_sync(0xffffffffu, a, off);
            if (lane == 0) out[b * 3 + o] = a + b_out[o];
        }
    }
}

// ---------------- launch -----------------------------------------------------
extern "C" void kernel_launch(void* const* d_in, const int* in_sizes, int n_in,
                              void* d_out, int out_size)
{
    const float* x           = (const float*)d_in[0];
    const int*   x_len       = (const int*)d_in[1];
    const float* target_word = (const float*)d_in[3];
    const float* W_ih_f      = (const float*)d_in[5];
    const float* W_hh_f      = (const float*)d_in[6];
    const float* b_f         = (const float*)d_in[7];
    const float* W_ih_b      = (const float*)d_in[8];
    const float* W_hh_b      = (const float*)d_in[9];
    const float* b_b         = (const float*)d_in[10];
    const float* W_h         = (const float*)d_in[11];
    const float* b_tanh      = (const float*)d_in[12];
    const float* W_lin       = (const float*)d_in[13];
    const float* b_lin       = (const float*)d_in[14];
    const float* W_out       = (const float*)d_in[15];
    const float* b_out       = (const float*)d_in[16];
    float* out = (float*)d_out;

    init_hc_kernel<<<(BB * HH + 255) / 256, 256>>>();
    convert_x_kernel<<<BB * LL, 256>>>(x);
    convert_w_kernel<<<GNF, 256>>>(W_ih_f, W_ih_b, b_f, b_b);

    dim3 ggrid(GNF / 128, MM_TOT / 128);   // (32, 256)
    gemm_mma_kernel<<<ggrid, 256>>>();

    dim3 sgrid(HH / 16, BB / 64, 2);       // (32, 4, 2)
    for (int t = 0; t < LL; t++)
        lstm_step_kernel<<<sgrid, 256>>>(x_len, W_hh_f, W_hh_b, t);

    final_kernel<<<BB, 256>>>(x, x_len, target_word, W_h, b_tanh,
                              W_lin, b_lin, W_out, b_out, out);
}

// round 5
// speedup vs baseline: 2.0373x; 1.2384x over previous
#include <cuda_runtime.h>
#include <cuda_bf16.h>
#include <math.h>
#include <stdint.h>

// Problem dims
#define BB 256
#define LL 128
#define DD 1024
#define HH 512
#define G4H 2048   // 4*H
#define GNF 4096   // fused gate dim (fwd 2048 | bwd 2048)
#define KS 3072    // input split-K: [hi|lo|hi] x [hi|hi|lo]
#define MM_TOT (LL * BB)   // 32768

// ---------------- scratch (device globals) ----------------------------------
__device__ float g_G[(size_t)MM_TOT * GNF];          // [(t*B+b)*4096 + c]
__device__ float g_outd[2][(size_t)BB * LL * HH];    // [dir][(b*L+t)*H + j]
__device__ float g_h[2][2][(size_t)BB * HH];         // fp32 h state
__device__ float g_c[2][2][(size_t)BB * HH];
__device__ __nv_bfloat16 g_hhi[2][2][(size_t)BB * HH];  // bf16 split h
__device__ __nv_bfloat16 g_hlo[2][2][(size_t)BB * HH];
__device__ __nv_bfloat16 g_Xs[(size_t)MM_TOT * KS];  // A' = [Xhi|Xlo|Xhi]
__device__ __nv_bfloat16 g_Ws[(size_t)GNF * KS];     // B' = [Whi|Whi|Wlo]
__device__ __nv_bfloat16 g_Whh[2][(size_t)G4H * 1024]; // [dir][c][ Whi(512) | Wlo(512) ], c gate-interleaved
__device__ float g_bias[GNF];

// ---------------- helpers ----------------------------------------------------
__device__ __forceinline__ uint32_t smem_u32(const void* p) {
    uint32_t a;
    asm("{ .reg .u64 t; cvta.to.shared.u64 t, %1; cvt.u32.u64 %0, t; }"
        : "=r"(a) : "l"(p));
    return a;
}
#define CPA16(dst, src) \
    asm volatile("cp.async.ca.shared.global [%0], [%1], 16;" :: "r"(dst), "l"(src))
#define CPA_COMMIT() asm volatile("cp.async.commit_group;" ::: "memory")

__device__ __forceinline__ void ldmatrix_x4(uint32_t* r, uint32_t addr) {
    asm volatile("ldmatrix.sync.aligned.m8n8.x4.shared.b16 {%0,%1,%2,%3}, [%4];"
                 : "=r"(r[0]), "=r"(r[1]), "=r"(r[2]), "=r"(r[3]) : "r"(addr));
}
__device__ __forceinline__ void mma16816(float* c, const uint32_t* a,
                                         uint32_t b0, uint32_t b1) {
    asm volatile(
        "mma.sync.aligned.m16n8k16.row.col.f32.bf16.bf16.f32 "
        "{%0,%1,%2,%3}, {%4,%5,%6,%7}, {%8,%9}, {%0,%1,%2,%3};"
        : "+f"(c[0]), "+f"(c[1]), "+f"(c[2]), "+f"(c[3])
        : "r"(a[0]), "r"(a[1]), "r"(a[2]), "r"(a[3]), "r"(b0), "r"(b1));
}

// ---------------- init -------------------------------------------------------
__global__ void init_hc_kernel() {
    int i = blockIdx.x * blockDim.x + threadIdx.x;
    if (i < BB * HH) {
        g_h[0][0][i] = 0.f; g_h[1][0][i] = 0.f;
        g_c[0][0][i] = 0.f; g_c[1][0][i] = 0.f;
        g_hhi[0][0][i] = __float2bfloat16_rn(0.f);
        g_hhi[1][0][i] = __float2bfloat16_rn(0.f);
        g_hlo[0][0][i] = __float2bfloat16_rn(0.f);
        g_hlo[1][0][i] = __float2bfloat16_rn(0.f);
    }
}

// ---------------- fp32 -> bf16 hi/lo split converters ------------------------
__global__ __launch_bounds__(256)
void convert_x_kernel(const float* __restrict__ X) {
    const int bt = blockIdx.x;            // b*L + t
    const int b = bt >> 7;
    const int t = bt & 127;
    const float4 v = ((const float4*)(X + (size_t)bt * DD))[threadIdx.x];
    __nv_bfloat16 hi4[4], lo4[4];
    hi4[0] = __float2bfloat16_rn(v.x); lo4[0] = __float2bfloat16_rn(v.x - __bfloat162float(hi4[0]));
    hi4[1] = __float2bfloat16_rn(v.y); lo4[1] = __float2bfloat16_rn(v.y - __bfloat162float(hi4[1]));
    hi4[2] = __float2bfloat16_rn(v.z); lo4[2] = __float2bfloat16_rn(v.z - __bfloat162float(hi4[2]));
    hi4[3] = __float2bfloat16_rn(v.w); lo4[3] = __float2bfloat16_rn(v.w - __bfloat162float(hi4[3]));
    const size_t base = ((size_t)t * BB + b) * KS + threadIdx.x * 4;
    *(uint2*)&g_Xs[base]        = *(const uint2*)hi4;
    *(uint2*)&g_Xs[base + DD]   = *(const uint2*)lo4;
    *(uint2*)&g_Xs[base + 2*DD] = *(const uint2*)hi4;
}

__global__ __launch_bounds__(256)
void convert_w_kernel(const float* __restrict__ Wf, const float* __restrict__ Wb,
                      const float* __restrict__ bf, const float* __restrict__ bb) {
    const int n = blockIdx.x;             // 0..4095
    const float* src = (n < G4H) ? (Wf + (size_t)n * DD)
                                 : (Wb + (size_t)(n - G4H) * DD);
    const float4 v = ((const float4*)src)[threadIdx.x];
    __nv_bfloat16 hi4[4], lo4[4];
    hi4[0] = __float2bfloat16_rn(v.x); lo4[0] = __float2bfloat16_rn(v.x - __bfloat162float(hi4[0]));
    hi4[1] = __float2bfloat16_rn(v.y); lo4[1] = __float2bfloat16_rn(v.y - __bfloat162float(hi4[1]));
    hi4[2] = __float2bfloat16_rn(v.z); lo4[2] = __float2bfloat16_rn(v.z - __bfloat162float(hi4[2]));
    hi4[3] = __float2bfloat16_rn(v.w); lo4[3] = __float2bfloat16_rn(v.w - __bfloat162float(hi4[3]));
    const size_t base = (size_t)n * KS + threadIdx.x * 4;
    *(uint2*)&g_Ws[base]        = *(const uint2*)hi4;
    *(uint2*)&g_Ws[base + DD]   = *(const uint2*)hi4;
    *(uint2*)&g_Ws[base + 2*DD] = *(const uint2*)lo4;
    if (threadIdx.x == 0)
        g_bias[n] = (n < G4H) ? bf[n] : bb[n - G4H];
}

// W_hh split: gate-interleaved rows c -> gate=c&3, j=c>>2; cols [hi(512)|lo(512)]
__global__ __launch_bounds__(128)
void convert_whh_kernel(const float* __restrict__ Wf, const float* __restrict__ Wb) {
    const int c   = blockIdx.x;           // 0..2047
    const int dir = blockIdx.y;
    const int gate = c & 3, j = c >> 2;
    const float* __restrict__ W = dir ? Wb : Wf;
    const float4 v = ((const float4*)(W + (size_t)(gate * HH + j) * HH))[threadIdx.x];
    __nv_bfloat16 hi4[4], lo4[4];
    hi4[0] = __float2bfloat16_rn(v.x); lo4[0] = __float2bfloat16_rn(v.x - __bfloat162float(hi4[0]));
    hi4[1] = __float2bfloat16_rn(v.y); lo4[1] = __float2bfloat16_rn(v.y - __bfloat162float(hi4[1]));
    hi4[2] = __float2bfloat16_rn(v.z); lo4[2] = __float2bfloat16_rn(v.z - __bfloat162float(hi4[2]));
    hi4[3] = __float2bfloat16_rn(v.w); lo4[3] = __float2bfloat16_rn(v.w - __bfloat162float(hi4[3]));
    __nv_bfloat16* dst = &g_Whh[dir][(size_t)c * 1024];
    *(uint2*)&dst[threadIdx.x * 4]       = *(const uint2*)hi4;
    *(uint2*)&dst[512 + threadIdx.x * 4] = *(const uint2*)lo4;
}

// ---------------- mma.sync input-projection GEMM (unchanged from R4) ---------
#define NKT (KS / 32)
#define SROW 80
#define STILE (128 * SROW)

__global__ __launch_bounds__(256, 2)
void gemm_mma_kernel() {
    __shared__ __align__(16) char smA[2][STILE];
    __shared__ __align__(16) char smB[2][STILE];

    const int tid  = threadIdx.x;
    const int wid  = tid >> 5;
    const int lane = tid & 31;
    const int nTile = blockIdx.x * 128;
    const int mTile = blockIdx.y * 128;

    const int wm = wid & 3;
    const int wn = wid >> 2;
    const int m0 = wm * 32;
    const int n0 = wn * 64;

    const int lrow = tid >> 1;
    const int lk   = tid & 1;
    const __nv_bfloat16* __restrict__ gA =
        g_Xs + (size_t)(mTile + lrow) * KS + lk * 16;
    const __nv_bfloat16* __restrict__ gB =
        g_Ws + (size_t)(nTile + lrow) * KS + lk * 16;

    const uint32_t baseA = smem_u32(smA);
    const uint32_t baseB = smem_u32(smB);
    const uint32_t stDstA = baseA + lrow * SROW + lk * 32;
    const uint32_t stDstB = baseB + lrow * SROW + lk * 32;

    float acc[2][8][4];
#pragma unroll
    for (int i = 0; i < 2; i++)
#pragma unroll
        for (int j = 0; j < 8; j++)
#pragma unroll
            for (int q = 0; q < 4; q++) acc[i][j][q] = 0.f;

    const int r8 = lane & 7;
    const int tI = lane >> 3;
    const uint32_t aLaneOff = (uint32_t)((r8 + (tI & 1) * 8) * SROW + (tI >> 1) * 16);
    const uint32_t bLaneOff = (uint32_t)((r8 + (tI >> 1) * 8) * SROW + (tI & 1) * 16);

    CPA16(stDstA, gA);        CPA16(stDstA + 16, gA + 8);
    CPA16(stDstB, gB);        CPA16(stDstB + 16, gB + 8);
    CPA_COMMIT();

    int buf = 0;
    for (int kt = 0; kt < NKT; kt++) {
        if (kt < NKT - 1) {
            const __nv_bfloat16* pa = gA + (size_t)(kt + 1) * 32;
            const __nv_bfloat16* pb = gB + (size_t)(kt + 1) * 32;
            const uint32_t dA = stDstA + (buf ^ 1) * STILE;
            const uint32_t dB = stDstB + (buf ^ 1) * STILE;
            CPA16(dA, pa); CPA16(dA + 16, pa + 8);
            CPA16(dB, pb); CPA16(dB + 16, pb + 8);
            CPA_COMMIT();
            asm volatile("cp.async.wait_group 1;" ::: "memory");
        } else {
            asm volatile("cp.async.wait_group 0;" ::: "memory");
        }
        __syncthreads();

        const uint32_t abuf = baseA + buf * STILE;
        const uint32_t bbuf = baseB + buf * STILE;
#pragma unroll
        for (int kk = 0; kk < 2; kk++) {
            uint32_t afr[2][4], bfr[4][4];
#pragma unroll
            for (int mi = 0; mi < 2; mi++)
                ldmatrix_x4(afr[mi],
                            abuf + (uint32_t)((m0 + mi * 16) * SROW + kk * 32) + aLaneOff);
#pragma unroll
            for (int nb = 0; nb < 4; nb++)
                ldmatrix_x4(bfr[nb],
                            bbuf + (uint32_t)((n0 + nb * 16) * SROW + kk * 32) + bLaneOff);
#pragma unroll
            for (int mi = 0; mi < 2; mi++)
#pragma unroll
                for (int ni = 0; ni < 8; ni++) {
                    const uint32_t* bp = &bfr[ni >> 1][(ni & 1) * 2];
                    mma16816(acc[mi][ni], afr[mi], bp[0], bp[1]);
                }
        }
        __syncthreads();
        buf ^= 1;
    }

    const int gid = lane >> 2;
    const int tig = lane & 3;
#pragma unroll
    for (int mi = 0; mi < 2; mi++) {
        const int m = mTile + m0 + mi * 16 + gid;
#pragma unroll
        for (int ni = 0; ni < 8; ni++) {
            const int n = nTile + n0 + ni * 8 + tig * 2;
            const float2 bv = *(const float2*)&g_bias[n];
            float2 o0 = make_float2(acc[mi][ni][0] + bv.x, acc[mi][ni][1] + bv.y);
            float2 o1 = make_float2(acc[mi][ni][2] + bv.x, acc[mi][ni][3] + bv.y);
            *(float2*)&g_G[(size_t)m * GNF + n]       = o0;
            *(float2*)&g_G[(size_t)(m + 8) * GNF + n] = o1;
        }
    }
}

// ---------------- tensor-core recurrent step ---------------------------------
// R[b, c] = h[b,:] . Whh_split_row(c)  (3-term split, K=1536),
// tile 64 batch x 128 gate-cols, grid (16, 4, 2) = 128 blocks, 256 threads.
// SMEM: A/B cp.async buffers overlaid later by R staging buffer.
#define RKT 48                  // 48 k-tiles of 32
#define RA_TILE (64 * SROW)     // 5120 B
#define RB_TILE (128 * SROW)    // 10240 B
#define ROFF_B  (2 * RA_TILE)   // B buffers after A buffers
#define R_SMEM  (64 * 132 * 4)  // 33792 B  (> 2*5120 + 2*10240 = 30720)

__global__ __launch_bounds__(256)
void lstm_mma_step(const int* __restrict__ x_len, int t)
{
    extern __shared__ __align__(16) char sm[];
    const uint32_t sbase = smem_u32(sm);
    float* __restrict__ sR = (float*)sm;

    const int tid  = threadIdx.x;
    const int wid  = tid >> 5;
    const int lane = tid & 31;
    const int nTile = blockIdx.x * 128;
    const int b0    = blockIdx.y * 64;
    const int dir   = blockIdx.z;

    const int p = t & 1;
    const __nv_bfloat16* __restrict__ hhi = g_hhi[dir][p];
    const __nv_bfloat16* __restrict__ hlo = g_hlo[dir][p];
    const float* __restrict__ hprev = g_h[dir][p];
    const float* __restrict__ cprev = g_c[dir][p];
    float* __restrict__ hnext = g_h[dir][p ^ 1];
    float* __restrict__ cnext = g_c[dir][p ^ 1];
    __nv_bfloat16* __restrict__ hhin = g_hhi[dir][p ^ 1];
    __nv_bfloat16* __restrict__ hlon = g_hlo[dir][p ^ 1];
    const __nv_bfloat16* __restrict__ Wd = g_Whh[dir];
    float* __restrict__ outp = g_outd[dir];

    // load mappings
    const int arow = tid >> 2;           // 0..63
    const int ac4  = (tid & 3) * 8;      // bf16 col offset {0,8,16,24}
    const int brow = tid >> 1;           // 0..127
    const int bc   = (tid & 1) * 16;     // {0,16}
    const uint32_t dstA0 = sbase + arow * SROW + (tid & 3) * 16;
    const uint32_t dstB0 = sbase + ROFF_B + brow * SROW + (tid & 1) * 32;
    const __nv_bfloat16* __restrict__ wrow = Wd + (size_t)(nTile + brow) * 1024 + bc;

    // warp tiles: 2m x 4n, warp tile 32x32
    const int m0 = (wid & 1) * 32;
    const int n0 = (wid >> 1) * 32;
    const int r8 = lane & 7;
    const int tI = lane >> 3;
    const uint32_t aLaneOff = (uint32_t)((r8 + (tI & 1) * 8) * SROW + (tI >> 1) * 16);
    const uint32_t bLaneOff = (uint32_t)((r8 + (tI >> 1) * 8) * SROW + (tI & 1) * 16);

    float acc[2][4][4];
#pragma unroll
    for (int i = 0; i < 2; i++)
#pragma unroll
        for (int j = 0; j < 4; j++)
#pragma unroll
            for (int q = 0; q < 4; q++) acc[i][j][q] = 0.f;

    // tile kt: seg = kt/16; A src: seg==1 ? hlo : hhi; acol = (kt&15)*32
    //          B col: seg0 kt*32 | seg1 (kt-16)*32 | seg2 512+(kt-32)*32
    {   // prologue tile 0
        const __nv_bfloat16* asrc = hhi + (size_t)(b0 + arow) * HH + ac4;
        CPA16(dstA0, asrc);
        CPA16(dstB0, wrow);
        CPA16(dstB0 + 16, wrow + 8);
        CPA_COMMIT();
    }

    int buf = 0;
    for (int kt = 0; kt < RKT; kt++) {
        if (kt < RKT - 1) {
            const int nk = kt + 1;
            const int seg = nk >> 4;
            const int acol = (nk & 15) * 32;
            const int bcol = (seg == 2) ? (512 + (nk - 32) * 32)
                                        : ((nk & 15) * 32);
            const __nv_bfloat16* asrc =
                ((seg == 1) ? hlo : hhi) + (size_t)(b0 + arow) * HH + acol + ac4;
            const __nv_bfloat16* bsrc = wrow + bcol;
            const uint32_t dA = dstA0 + (buf ^ 1) * RA_TILE;
            const uint32_t dB = dstB0 + (buf ^ 1) * RB_TILE;
            CPA16(dA, asrc);
            CPA16(dB, bsrc);
            CPA16(dB + 16, bsrc + 8);
            CPA_COMMIT();
            asm volatile("cp.async.wait_group 1;" ::: "memory");
        } else {
            asm volatile("cp.async.wait_group 0;" ::: "memory");
        }
        __syncthreads();

        const uint32_t abuf = sbase + buf * RA_TILE;
        const uint32_t bbuf = sbase + ROFF_B + buf * RB_TILE;
#pragma unroll
        for (int kk = 0; kk < 2; kk++) {
            uint32_t afr[2][4], bfr[2][4];
#pragma unroll
            for (int mi = 0; mi < 2; mi++)
                ldmatrix_x4(afr[mi],
                            abuf + (uint32_t)((m0 + mi * 16) * SROW + kk * 32) + aLaneOff);
#pragma unroll
            for (int nb = 0; nb < 2; nb++)
                ldmatrix_x4(bfr[nb],
                            bbuf + (uint32_t)((n0 + nb * 16) * SROW + kk * 32) + bLaneOff);
#pragma unroll
            for (int mi = 0; mi < 2; mi++)
#pragma unroll
                for (int ni = 0; ni < 4; ni++) {
                    const uint32_t* bp = &bfr[ni >> 1][(ni & 1) * 2];
                    mma16816(acc[mi][ni], afr[mi], bp[0], bp[1]);
                }
        }
        __syncthreads();
        buf ^= 1;
    }

    // stage R through smem (overwrites A/B buffers; all MMA data is in regs)
    __syncthreads();
    const int gid = lane >> 2;
    const int tig = lane & 3;
#pragma unroll
    for (int mi = 0; mi < 2; mi++) {
        const int row = m0 + mi * 16 + gid;
#pragma unroll
        for (int ni = 0; ni < 4; ni++) {
            const int col = n0 + ni * 8 + tig * 2;
            sR[row * 132 + col]           = acc[mi][ni][0];
            sR[row * 132 + col + 1]       = acc[mi][ni][1];
            sR[(row + 8) * 132 + col]     = acc[mi][ni][2];
            sR[(row + 8) * 132 + col + 1] = acc[mi][ni][3];
        }
    }
    __syncthreads();

    // fused LSTM pointwise: 2048 elems / 256 threads = 8 each
    const int jBase = nTile >> 2;
#pragma unroll
    for (int it = 0; it < 8; it++) {
        const int idx = it * 256 + tid;
        const int bl = idx >> 5;          // 0..63
        const int jj = idx & 31;          // 0..31
        const int b  = b0 + bl;
        const int j  = jBase + jj;
        const int len = x_len[b];
        int tq = t;
        if (dir) { tq = len - 1 - t; if (tq < 0) tq = 0; }
        const float* __restrict__ gpre =
            g_G + ((size_t)tq * BB + b) * GNF + dir * G4H + j;
        const float4 rv = *(const float4*)&sR[bl * 132 + jj * 4];
        float gi = rv.x + gpre[0];
        float gf = rv.y + gpre[HH];
        float gg = rv.z + gpre[2 * HH];
        float go = rv.w + gpre[3 * HH];
        float i_ = 1.f / (1.f + expf(-gi));
        float f_ = 1.f / (1.f + expf(-gf));
        float g_ = tanhf(gg);
        float o_ = 1.f / (1.f + expf(-go));
        const size_t hc = (size_t)b * HH + j;
        float cp = cprev[hc];
        float hp = hprev[hc];
        float cn = f_ * cp + i_ * g_;
        float hn = o_ * tanhf(cn);
        const bool valid = (t < len);
        const float ho = valid ? hn : hp;
        const float co = valid ? cn : cp;
        hnext[hc] = ho;
        cnext[hc] = co;
        __nv_bfloat16 hi = __float2bfloat16_rn(ho);
        hhin[hc] = hi;
        hlon[hc] = __float2bfloat16_rn(ho - __bfloat162float(hi));
        outp[((size_t)b * LL + t) * HH + j] = valid ? hn : 0.f;
    }
}

// ---------------- attention + head (one block per batch) ---------------------
__global__ __launch_bounds__(256)
void final_kernel(const float* __restrict__ x, const int* __restrict__ x_len,
                  const float* __restrict__ target_word,
                  const float* __restrict__ W_h, const float* __restrict__ b_tanh,
                  const float* __restrict__ W_lin, const float* __restrict__ b_lin,
                  const float* __restrict__ W_out, const float* __restrict__ b_out,
                  float* __restrict__ out)
{
    __shared__ float s_u[LL];
    __shared__ float s_ctx[2 * HH];
    __shared__ float s_lin[512];
    __shared__ float s_red[8];
    __shared__ float s_twdot;

    const int b    = blockIdx.x;
    const int tid  = threadIdx.x;
    const int warp = tid >> 5;
    const int lane = tid & 31;
    const int len  = x_len[b];

    {
        float partial = 0.f;
        for (int d = tid; d < DD; d += 256) {
            float s = 0.f;
#pragma unroll
            for (int k = 0; k < 5; k++)
                s += target_word[((size_t)b * 5 + k) * DD + d];
            partial = fmaf(s * 0.2f, W_h[DD + d], partial);
        }
#pragma unroll
        for (int off = 16; off; off >>= 1)
            partial += __shfl_xor_sync(0xffffffffu, partial, off);
        if (lane == 0) s_red[warp] = partial;
        __syncthreads();
        if (tid == 0) {
            float s = 0.f;
            for (int w = 0; w < 8; w++) s += s_red[w];
            s_twdot = s;
        }
        __syncthreads();
    }
    const float twdot = s_twdot;

    for (int i = 0; i < 16; i++) {
        const int t = warp * 16 + i;
        const float* xe = x + ((size_t)b * LL + t) * DD;
        float a = 0.f;
#pragma unroll 8
        for (int q = 0; q < 32; q++) {
            int d = lane + q * 32;
            a = fmaf(xe[d], W_h[d], a);
        }
#pragma unroll
        for (int off = 16; off; off >>= 1)
            a += __shfl_xor_sync(0xffffffffu, a, off);
        if (lane == 0)
            s_u[t] = (t < len) ? (a + twdot + b_tanh[t]) : -1e6f;
    }
    __syncthreads();

    if (warp == 0) {
        float v[4];
#pragma unroll
        for (int q = 0; q < 4; q++) v[q] = s_u[lane + q * 32];
        float m = fmaxf(fmaxf(v[0], v[1]), fmaxf(v[2], v[3]));
#pragma unroll
        for (int off = 16; off; off >>= 1)
            m = fmaxf(m, __shfl_xor_sync(0xffffffffu, m, off));
        float e[4], s = 0.f;
#pragma unroll
        for (int q = 0; q < 4; q++) { e[q] = expf(v[q] - m); s += e[q]; }
#pragma unroll
        for (int off = 16; off; off >>= 1)
            s += __shfl_xor_sync(0xffffffffu, s, off);
        float inv = 1.f / s;
#pragma unroll
        for (int q = 0; q < 4; q++) s_u[lane + q * 32] = e[q] * inv;
    }
    __syncthreads();

    {
        float accj[4] = {0.f, 0.f, 0.f, 0.f};
        const float* outf = g_outd[0] + (size_t)b * LL * HH;
        const float* outb = g_outd[1] + (size_t)b * LL * HH;
        for (int t = 0; t < LL; t++) {
            const float a = s_u[t];
            int t2 = len - 1 - t;
            if (t2 < 0) t2 = 0;
#pragma unroll
            for (int q = 0; q < 4; q++) {
                const int j = tid + q * 256;
                float hv;
                if (j < HH) hv = outf[(size_t)t * HH + j];
                else        hv = outb[(size_t)t2 * HH + (j - HH)];
                accj[q] = fmaf(a, hv, accj[q]);
            }
        }
#pragma unroll
        for (int q = 0; q < 4; q++) s_ctx[tid + q * 256] = accj[q];
    }
    __syncthreads();

    for (int i = 0; i < 64; i++) {
        const int o = warp * 64 + i;
        const float* wr = W_lin + (size_t)o * (2 * HH);
        float a = 0.f;
#pragma unroll 8
        for (int q = 0; q < 32; q++) {
            int d = lane + q * 32;
            a = fmaf(s_ctx[d], wr[d], a);
        }
#pragma unroll
        for (int off = 16; off; off >>= 1)
            a += __shfl_xor_sync(0xffffffffu, a, off);
        if (lane == 0) s_lin[o] = fmaxf(a + b_lin[o], 0.f);
    }
    __syncthreads();

    if (warp == 0) {
#pragma unroll
        for (int o = 0; o < 3; o++) {
            const float* wr = W_out + (size_t)o * 512;
            float a = 0.f;
#pragma unroll
            for (int q = 0; q < 16; q++) {
                int d = lane + q * 32;
                a = fmaf(s_lin[d], wr[d], a);
            }
#pragma unroll
            for (int off = 16; off; off >>= 1)
                a += __shfl_xor_sync(0xffffffffu, a, off);
            if (lane == 0) out[b * 3 + o] = a + b_out[o];
        }
    }
}

// ---------------- launch -----------------------------------------------------
extern "C" void kernel_launch(void* const* d_in, const int* in_sizes, int n_in,
                              void* d_out, int out_size)
{
    const float* x           = (const float*)d_in[0];
    const int*   x_len       = (const int*)d_in[1];
    const float* target_word = (const float*)d_in[3];
    const float* W_ih_f      = (const float*)d_in[5];
    const float* W_hh_f      = (const float*)d_in[6];
    const float* b_f         = (const float*)d_in[7];
    const float* W_ih_b      = (const float*)d_in[8];
    const float* W_hh_b      = (const float*)d_in[9];
    const float* b_b         = (const float*)d_in[10];
    const float* W_h         = (const float*)d_in[11];
    const float* b_tanh      = (const float*)d_in[12];
    const float* W_lin       = (const float*)d_in[13];
    const float* b_lin       = (const float*)d_in[14];
    const float* W_out       = (const float*)d_in[15];
    const float* b_out       = (const float*)d_in[16];
    float* out = (float*)d_out;

    init_hc_kernel<<<(BB * HH + 255) / 256, 256>>>();
    convert_x_kernel<<<BB * LL, 256>>>(x);
    convert_w_kernel<<<GNF, 256>>>(W_ih_f, W_ih_b, b_f, b_b);
    {
        dim3 wgrid(G4H, 2);
        convert_whh_kernel<<<wgrid, 128>>>(W_hh_f, W_hh_b);
    }

    dim3 ggrid(GNF / 128, MM_TOT / 128);   // (32, 256)
    gemm_mma_kernel<<<ggrid, 256>>>();

    dim3 sgrid(G4H / 128, BB / 64, 2);     // (16, 4, 2)
    for (int t = 0; t < LL; t++)
        lstm_mma_step<<<sgrid, 256, R_SMEM>>>(x_len, t);

    final_kernel<<<BB, 256>>>(x, x_len, target_word, W_h, b_tanh,
                              W_lin, b_lin, W_out, b_out, out);
}

// round 6
// speedup vs baseline: 2.2574x; 1.1080x over previous
#include <cuda_runtime.h>
#include <cuda_bf16.h>
#include <math.h>
#include <stdint.h>

// Problem dims
#define BB 256
#define LL 128
#define DD 1024
#define HH 512
#define G4H 2048
#define GNF 4096
#define KS 3072
#define MM_TOT (LL * BB)

// ---------------- scratch (device globals) ----------------------------------
__device__ float g_G[(size_t)MM_TOT * GNF];          // [(t*B+b)*4096 + c], c gate-interleaved
__device__ float g_outd[2][(size_t)BB * LL * HH];
__device__ float g_h[2][2][(size_t)BB * HH];
__device__ float g_c[2][2][(size_t)BB * HH];
__device__ __nv_bfloat16 g_hhi[2][2][(size_t)BB * HH];
__device__ __nv_bfloat16 g_hlo[2][2][(size_t)BB * HH];
__device__ __nv_bfloat16 g_Xs[(size_t)MM_TOT * KS];
__device__ __nv_bfloat16 g_Ws[(size_t)GNF * KS];     // rows gate-interleaved
__device__ __nv_bfloat16 g_Whh[2][(size_t)G4H * 1024]; // [dir][c][Whi(512)|Wlo(512)], c interleaved
__device__ float g_bias[GNF];                        // gate-interleaved

// ---------------- helpers ----------------------------------------------------
__device__ __forceinline__ uint32_t smem_u32(const void* p) {
    uint32_t a;
    asm("{ .reg .u64 t; cvta.to.shared.u64 t, %1; cvt.u32.u64 %0, t; }"
        : "=r"(a) : "l"(p));
    return a;
}
#define CPA16(dst, src) \
    asm volatile("cp.async.ca.shared.global [%0], [%1], 16;" :: "r"(dst), "l"(src))
#define CPA_COMMIT() asm volatile("cp.async.commit_group;" ::: "memory")

__device__ __forceinline__ void ldmatrix_x4(uint32_t* r, uint32_t addr) {
    asm volatile("ldmatrix.sync.aligned.m8n8.x4.shared.b16 {%0,%1,%2,%3}, [%4];"
                 : "=r"(r[0]), "=r"(r[1]), "=r"(r[2]), "=r"(r[3]) : "r"(addr));
}
__device__ __forceinline__ void mma16816(float* c, const uint32_t* a,
                                         uint32_t b0, uint32_t b1) {
    asm volatile(
        "mma.sync.aligned.m16n8k16.row.col.f32.bf16.bf16.f32 "
        "{%0,%1,%2,%3}, {%4,%5,%6,%7}, {%8,%9}, {%0,%1,%2,%3};"
        : "+f"(c[0]), "+f"(c[1]), "+f"(c[2]), "+f"(c[3])
        : "r"(a[0]), "r"(a[1]), "r"(a[2]), "r"(a[3]), "r"(b0), "r"(b1));
}

// ---------------- init -------------------------------------------------------
__global__ void init_hc_kernel() {
    int i = blockIdx.x * blockDim.x + threadIdx.x;
    if (i < BB * HH) {
        g_h[0][0][i] = 0.f; g_h[1][0][i] = 0.f;
        g_c[0][0][i] = 0.f; g_c[1][0][i] = 0.f;
        g_hhi[0][0][i] = __float2bfloat16_rn(0.f);
        g_hhi[1][0][i] = __float2bfloat16_rn(0.f);
        g_hlo[0][0][i] = __float2bfloat16_rn(0.f);
        g_hlo[1][0][i] = __float2bfloat16_rn(0.f);
    }
}

// ---------------- fp32 -> bf16 hi/lo split converters ------------------------
__global__ __launch_bounds__(256)
void convert_x_kernel(const float* __restrict__ X) {
    const int bt = blockIdx.x;
    const int b = bt >> 7;
    const int t = bt & 127;
    const float4 v = ((const float4*)(X + (size_t)bt * DD))[threadIdx.x];
    __nv_bfloat16 hi4[4], lo4[4];
    hi4[0] = __float2bfloat16_rn(v.x); lo4[0] = __float2bfloat16_rn(v.x - __bfloat162float(hi4[0]));
    hi4[1] = __float2bfloat16_rn(v.y); lo4[1] = __float2bfloat16_rn(v.y - __bfloat162float(hi4[1]));
    hi4[2] = __float2bfloat16_rn(v.z); lo4[2] = __float2bfloat16_rn(v.z - __bfloat162float(hi4[2]));
    hi4[3] = __float2bfloat16_rn(v.w); lo4[3] = __float2bfloat16_rn(v.w - __bfloat162float(hi4[3]));
    const size_t base = ((size_t)t * BB + b) * KS + threadIdx.x * 4;
    *(uint2*)&g_Xs[base]        = *(const uint2*)hi4;
    *(uint2*)&g_Xs[base + DD]   = *(const uint2*)lo4;
    *(uint2*)&g_Xs[base + 2*DD] = *(const uint2*)hi4;
}

// permuted: output row c -> source row gate*512+j, c = dir*2048 + j*4 + gate
__global__ __launch_bounds__(256)
void convert_w_kernel(const float* __restrict__ Wf, const float* __restrict__ Wb,
                      const float* __restrict__ bf, const float* __restrict__ bb) {
    const int c = blockIdx.x;             // 0..4095 output row
    const int dir = (c >= G4H);
    const int local = c - dir * G4H;
    const int j = local >> 2, gate = local & 3;
    const int srow = gate * HH + j;
    const float* src = dir ? (Wb + (size_t)srow * DD) : (Wf + (size_t)srow * DD);
    const float4 v = ((const float4*)src)[threadIdx.x];
    __nv_bfloat16 hi4[4], lo4[4];
    hi4[0] = __float2bfloat16_rn(v.x); lo4[0] = __float2bfloat16_rn(v.x - __bfloat162float(hi4[0]));
    hi4[1] = __float2bfloat16_rn(v.y); lo4[1] = __float2bfloat16_rn(v.y - __bfloat162float(hi4[1]));
    hi4[2] = __float2bfloat16_rn(v.z); lo4[2] = __float2bfloat16_rn(v.z - __bfloat162float(hi4[2]));
    hi4[3] = __float2bfloat16_rn(v.w); lo4[3] = __float2bfloat16_rn(v.w - __bfloat162float(hi4[3]));
    const size_t base = (size_t)c * KS + threadIdx.x * 4;
    *(uint2*)&g_Ws[base]        = *(const uint2*)hi4;
    *(uint2*)&g_Ws[base + DD]   = *(const uint2*)hi4;
    *(uint2*)&g_Ws[base + 2*DD] = *(const uint2*)lo4;
    if (threadIdx.x == 0)
        g_bias[c] = dir ? bb[srow] : bf[srow];
}

__global__ __launch_bounds__(128)
void convert_whh_kernel(const float* __restrict__ Wf, const float* __restrict__ Wb) {
    const int c   = blockIdx.x;           // 0..2047
    const int dir = blockIdx.y;
    const int gate = c & 3, j = c >> 2;
    const float* __restrict__ W = dir ? Wb : Wf;
    const float4 v = ((const float4*)(W + (size_t)(gate * HH + j) * HH))[threadIdx.x];
    __nv_bfloat16 hi4[4], lo4[4];
    hi4[0] = __float2bfloat16_rn(v.x); lo4[0] = __float2bfloat16_rn(v.x - __bfloat162float(hi4[0]));
    hi4[1] = __float2bfloat16_rn(v.y); lo4[1] = __float2bfloat16_rn(v.y - __bfloat162float(hi4[1]));
    hi4[2] = __float2bfloat16_rn(v.z); lo4[2] = __float2bfloat16_rn(v.z - __bfloat162float(hi4[2]));
    hi4[3] = __float2bfloat16_rn(v.w); lo4[3] = __float2bfloat16_rn(v.w - __bfloat162float(hi4[3]));
    __nv_bfloat16* dst = &g_Whh[dir][(size_t)c * 1024];
    *(uint2*)&dst[threadIdx.x * 4]       = *(const uint2*)hi4;
    *(uint2*)&dst[512 + threadIdx.x * 4] = *(const uint2*)lo4;
}

// ---------------- mma.sync input-projection GEMM (validated R4) --------------
#define NKT (KS / 32)
#define SROW 80
#define STILE (128 * SROW)

__global__ __launch_bounds__(256, 2)
void gemm_mma_kernel() {
    __shared__ __align__(16) char smA[2][STILE];
    __shared__ __align__(16) char smB[2][STILE];

    const int tid  = threadIdx.x;
    const int wid  = tid >> 5;
    const int lane = tid & 31;
    const int nTile = blockIdx.x * 128;
    const int mTile = blockIdx.y * 128;

    const int wm = wid & 3;
    const int wn = wid >> 2;
    const int m0 = wm * 32;
    const int n0 = wn * 64;

    const int lrow = tid >> 1;
    const int lk   = tid & 1;
    const __nv_bfloat16* __restrict__ gA =
        g_Xs + (size_t)(mTile + lrow) * KS + lk * 16;
    const __nv_bfloat16* __restrict__ gB =
        g_Ws + (size_t)(nTile + lrow) * KS + lk * 16;

    const uint32_t baseA = smem_u32(smA);
    const uint32_t baseB = smem_u32(smB);
    const uint32_t stDstA = baseA + lrow * SROW + lk * 32;
    const uint32_t stDstB = baseB + lrow * SROW + lk * 32;

    float acc[2][8][4];
#pragma unroll
    for (int i = 0; i < 2; i++)
#pragma unroll
        for (int j = 0; j < 8; j++)
#pragma unroll
            for (int q = 0; q < 4; q++) acc[i][j][q] = 0.f;

    const int r8 = lane & 7;
    const int tI = lane >> 3;
    const uint32_t aLaneOff = (uint32_t)((r8 + (tI & 1) * 8) * SROW + (tI >> 1) * 16);
    const uint32_t bLaneOff = (uint32_t)((r8 + (tI >> 1) * 8) * SROW + (tI & 1) * 16);

    CPA16(stDstA, gA);        CPA16(stDstA + 16, gA + 8);
    CPA16(stDstB, gB);        CPA16(stDstB + 16, gB + 8);
    CPA_COMMIT();

    int buf = 0;
    for (int kt = 0; kt < NKT; kt++) {
        if (kt < NKT - 1) {
            const __nv_bfloat16* pa = gA + (size_t)(kt + 1) * 32;
            const __nv_bfloat16* pb = gB + (size_t)(kt + 1) * 32;
            const uint32_t dA = stDstA + (buf ^ 1) * STILE;
            const uint32_t dB = stDstB + (buf ^ 1) * STILE;
            CPA16(dA, pa); CPA16(dA + 16, pa + 8);
            CPA16(dB, pb); CPA16(dB + 16, pb + 8);
            CPA_COMMIT();
            asm volatile("cp.async.wait_group 1;" ::: "memory");
        } else {
            asm volatile("cp.async.wait_group 0;" ::: "memory");
        }
        __syncthreads();

        const uint32_t abuf = baseA + buf * STILE;
        const uint32_t bbuf = baseB + buf * STILE;
#pragma unroll
        for (int kk = 0; kk < 2; kk++) {
            uint32_t afr[2][4], bfr[4][4];
#pragma unroll
            for (int mi = 0; mi < 2; mi++)
                ldmatrix_x4(afr[mi],
                            abuf + (uint32_t)((m0 + mi * 16) * SROW + kk * 32) + aLaneOff);
#pragma unroll
            for (int nb = 0; nb < 4; nb++)
                ldmatrix_x4(bfr[nb],
                            bbuf + (uint32_t)((n0 + nb * 16) * SROW + kk * 32) + bLaneOff);
#pragma unroll
            for (int mi = 0; mi < 2; mi++)
#pragma unroll
                for (int ni = 0; ni < 8; ni++) {
                    const uint32_t* bp = &bfr[ni >> 1][(ni & 1) * 2];
                    mma16816(acc[mi][ni], afr[mi], bp[0], bp[1]);
                }
        }
        __syncthreads();
        buf ^= 1;
    }

    const int gid = lane >> 2;
    const int tig = lane & 3;
#pragma unroll
    for (int mi = 0; mi < 2; mi++) {
        const int m = mTile + m0 + mi * 16 + gid;
#pragma unroll
        for (int ni = 0; ni < 8; ni++) {
            const int n = nTile + n0 + ni * 8 + tig * 2;
            const float2 bv = *(const float2*)&g_bias[n];
            float2 o0 = make_float2(acc[mi][ni][0] + bv.x, acc[mi][ni][1] + bv.y);
            float2 o1 = make_float2(acc[mi][ni][2] + bv.x, acc[mi][ni][3] + bv.y);
            *(float2*)&g_G[(size_t)m * GNF + n]       = o0;
            *(float2*)&g_G[(size_t)(m + 8) * GNF + n] = o1;
        }
    }
}

// ---------------- tensor-core recurrent step, 3-stage pipeline, BK=64 --------
#define SROW2 144                 // 64 bf16 (128B) + 16B pad
#define A2_TILE (64 * SROW2)      // 9216
#define B2_TILE (128 * SROW2)     // 18432
#define STG     (A2_TILE + B2_TILE)
#define R6_SMEM (3 * STG)         // 82944
#define RKT2 24                   // 1536 / 64

__global__ __launch_bounds__(256)
void lstm_mma_step(const int* __restrict__ x_len, int t)
{
    extern __shared__ __align__(16) char sm[];
    const uint32_t sbase = smem_u32(sm);
    float* __restrict__ sR = (float*)sm;

    const int tid  = threadIdx.x;
    const int wid  = tid >> 5;
    const int lane = tid & 31;
    const int nTile = blockIdx.x * 128;
    const int b0    = blockIdx.y * 64;
    const int dir   = blockIdx.z;

    const int p = t & 1;
    const __nv_bfloat16* __restrict__ hhi = g_hhi[dir][p];
    const __nv_bfloat16* __restrict__ hlo = g_hlo[dir][p];
    const float* __restrict__ hprev = g_h[dir][p];
    const float* __restrict__ cprev = g_c[dir][p];
    float* __restrict__ hnext = g_h[dir][p ^ 1];
    float* __restrict__ cnext = g_c[dir][p ^ 1];
    __nv_bfloat16* __restrict__ hhin = g_hhi[dir][p ^ 1];
    __nv_bfloat16* __restrict__ hlon = g_hlo[dir][p ^ 1];
    const __nv_bfloat16* __restrict__ Wd = g_Whh[dir];
    float* __restrict__ outp = g_outd[dir];

    // load mappings: A 512 chunks (2/thread), B 1024 chunks (4/thread)
    const int aRow0 = tid >> 3;            // chunk tid     -> rows 0..31
    const int aRow1 = (tid + 256) >> 3;    // chunk tid+256 -> rows 32..63
    const int aCol  = (tid & 7) * 8;       // elem offset within 64
    const uint32_t dA_off0 = (uint32_t)(aRow0 * SROW2 + (tid & 7) * 16);
    const uint32_t dA_off1 = (uint32_t)(aRow1 * SROW2 + (tid & 7) * 16);

    float acc[2][4][4];
#pragma unroll
    for (int i = 0; i < 2; i++)
#pragma unroll
        for (int j = 0; j < 4; j++)
#pragma unroll
            for (int q = 0; q < 4; q++) acc[i][j][q] = 0.f;

    // stage issue helper (inlined by macro-like lambda)
    auto issue_stage = [&](int kt, int stage) {
        const int seg  = kt >> 3;
        const int acol = (kt & 7) * 64;
        const int bcol = (seg == 2) ? (512 + (kt & 7) * 64) : ((kt & 7) * 64);
        const __nv_bfloat16* __restrict__ hsrc = (seg == 1) ? hlo : hhi;
        const uint32_t sa = sbase + stage * STG;
        const uint32_t sb = sa + A2_TILE;
        // A: 2 chunks
        CPA16(sa + dA_off0, hsrc + (size_t)(b0 + aRow0) * HH + acol + aCol);
        CPA16(sa + dA_off1, hsrc + (size_t)(b0 + aRow1) * HH + acol + aCol);
        // B: 4 chunks
#pragma unroll
        for (int q = 0; q < 4; q++) {
            const int chunk = tid + q * 256;
            const int br = chunk >> 3;
            const int bc = (chunk & 7) * 8;
            CPA16(sb + (uint32_t)(br * SROW2 + (chunk & 7) * 16),
                  Wd + (size_t)(nTile + br) * 1024 + bcol + bc);
        }
    };

    // warp tiling: 2m x 4n warps, warp tile 32x32
    const int m0 = (wid & 1) * 32;
    const int n0 = (wid >> 1) * 32;
    const int r8 = lane & 7;
    const int tI = lane >> 3;
    const uint32_t aLaneOff = (uint32_t)((r8 + (tI & 1) * 8) * SROW2 + (tI >> 1) * 16);
    const uint32_t bLaneOff = (uint32_t)((r8 + (tI >> 1) * 8) * SROW2 + (tI & 1) * 16);

    // prologue: stages for kt=0,1
    issue_stage(0, 0); CPA_COMMIT();
    issue_stage(1, 1); CPA_COMMIT();

    for (int kt = 0; kt < RKT2; kt++) {
        if (kt + 2 < RKT2) issue_stage(kt + 2, (kt + 2) % 3);
        CPA_COMMIT();
        asm volatile("cp.async.wait_group 2;" ::: "memory");
        __syncthreads();

        const uint32_t sa = sbase + (kt % 3) * STG;
        const uint32_t sb = sa + A2_TILE;
#pragma unroll
        for (int kk = 0; kk < 4; kk++) {
            uint32_t afr[2][4], bfr[2][4];
#pragma unroll
            for (int mi = 0; mi < 2; mi++)
                ldmatrix_x4(afr[mi],
                            sa + (uint32_t)((m0 + mi * 16) * SROW2 + kk * 32) + aLaneOff);
#pragma unroll
            for (int nb = 0; nb < 2; nb++)
                ldmatrix_x4(bfr[nb],
                            sb + (uint32_t)((n0 + nb * 16) * SROW2 + kk * 32) + bLaneOff);
#pragma unroll
            for (int mi = 0; mi < 2; mi++)
#pragma unroll
                for (int ni = 0; ni < 4; ni++) {
                    const uint32_t* bp = &bfr[ni >> 1][(ni & 1) * 2];
                    mma16816(acc[mi][ni], afr[mi], bp[0], bp[1]);
                }
        }
        __syncthreads();
    }

    // stage R through smem (overwrites pipeline buffers)
    const int gid = lane >> 2;
    const int tig = lane & 3;
#pragma unroll
    for (int mi = 0; mi < 2; mi++) {
        const int row = m0 + mi * 16 + gid;
#pragma unroll
        for (int ni = 0; ni < 4; ni++) {
            const int col = n0 + ni * 8 + tig * 2;
            sR[row * 132 + col]           = acc[mi][ni][0];
            sR[row * 132 + col + 1]       = acc[mi][ni][1];
            sR[(row + 8) * 132 + col]     = acc[mi][ni][2];
            sR[(row + 8) * 132 + col + 1] = acc[mi][ni][3];
        }
    }
    __syncthreads();

    // fused LSTM pointwise: 2048 elems, gate-interleaved float4 loads
    const int jBase = nTile >> 2;
#pragma unroll
    for (int it = 0; it < 8; it++) {
        const int idx = it * 256 + tid;
        const int bl = idx >> 5;
        const int jj = idx & 31;
        const int b  = b0 + bl;
        const int j  = jBase + jj;
        const int len = x_len[b];
        int tq = t;
        if (dir) { tq = len - 1 - t; if (tq < 0) tq = 0; }
        const float4 gp = *(const float4*)(
            g_G + ((size_t)tq * BB + b) * GNF + dir * G4H + (size_t)j * 4);
        const float4 rv = *(const float4*)&sR[bl * 132 + jj * 4];
        float gi = rv.x + gp.x;
        float gf = rv.y + gp.y;
        float gg = rv.z + gp.z;
        float go = rv.w + gp.w;
        float i_ = 1.f / (1.f + expf(-gi));
        float f_ = 1.f / (1.f + expf(-gf));
        float g_ = tanhf(gg);
        float o_ = 1.f / (1.f + expf(-go));
        const size_t hc = (size_t)b * HH + j;
        float cp = cprev[hc];
        float hp = hprev[hc];
        float cn = f_ * cp + i_ * g_;
        float hn = o_ * tanhf(cn);
        const bool valid = (t < len);
        const float ho = valid ? hn : hp;
        const float co = valid ? cn : cp;
        hnext[hc] = ho;
        cnext[hc] = co;
        __nv_bfloat16 hi = __float2bfloat16_rn(ho);
        hhin[hc] = hi;
        hlon[hc] = __float2bfloat16_rn(ho - __bfloat162float(hi));
        outp[((size_t)b * LL + t) * HH + j] = valid ? hn : 0.f;
    }
}

// ---------------- attention + head (one block per batch) ---------------------
__global__ __launch_bounds__(256)
void final_kernel(const float* __restrict__ x, const int* __restrict__ x_len,
                  const float* __restrict__ target_word,
                  const float* __restrict__ W_h, const float* __restrict__ b_tanh,
                  const float* __restrict__ W_lin, const float* __restrict__ b_lin,
                  const float* __restrict__ W_out, const float* __restrict__ b_out,
                  float* __restrict__ out)
{
    __shared__ float s_u[LL];
    __shared__ float s_ctx[2 * HH];
    __shared__ float s_lin[512];
    __shared__ float s_red[8];
    __shared__ float s_twdot;

    const int b    = blockIdx.x;
    const int tid  = threadIdx.x;
    const int warp = tid >> 5;
    const int lane = tid & 31;
    const int len  = x_len[b];

    {
        float partial = 0.f;
        for (int d = tid; d < DD; d += 256) {
            float s = 0.f;
#pragma unroll
            for (int k = 0; k < 5; k++)
                s += target_word[((size_t)b * 5 + k) * DD + d];
            partial = fmaf(s * 0.2f, W_h[DD + d], partial);
        }
#pragma unroll
        for (int off = 16; off; off >>= 1)
            partial += __shfl_xor_sync(0xffffffffu, partial, off);
        if (lane == 0) s_red[warp] = partial;
        __syncthreads();
        if (tid == 0) {
            float s = 0.f;
            for (int w = 0; w < 8; w++) s += s_red[w];
            s_twdot = s;
        }
        __syncthreads();
    }
    const float twdot = s_twdot;

    for (int i = 0; i < 16; i++) {
        const int t = warp * 16 + i;
        const float* xe = x + ((size_t)b * LL + t) * DD;
        float a = 0.f;
#pragma unroll 8
        for (int q = 0; q < 32; q++) {
            int d = lane + q * 32;
            a = fmaf(xe[d], W_h[d], a);
        }
#pragma unroll
        for (int off = 16; off; off >>= 1)
            a += __shfl_xor_sync(0xffffffffu, a, off);
        if (lane == 0)
            s_u[t] = (t < len) ? (a + twdot + b_tanh[t]) : -1e6f;
    }
    __syncthreads();

    if (warp == 0) {
        float v[4];
#pragma unroll
        for (int q = 0; q < 4; q++) v[q] = s_u[lane + q * 32];
        float m = fmaxf(fmaxf(v[0], v[1]), fmaxf(v[2], v[3]));
#pragma unroll
        for (int off = 16; off; off >>= 1)
            m = fmaxf(m, __shfl_xor_sync(0xffffffffu, m, off));
        float e[4], s = 0.f;
#pragma unroll
        for (int q = 0; q < 4; q++) { e[q] = expf(v[q] - m); s += e[q]; }
#pragma unroll
        for (int off = 16; off; off >>= 1)
            s += __shfl_xor_sync(0xffffffffu, s, off);
        float inv = 1.f / s;
#pragma unroll
        for (int q = 0; q < 4; q++) s_u[lane + q * 32] = e[q] * inv;
    }
    __syncthreads();

    {
        float accj[4] = {0.f, 0.f, 0.f, 0.f};
        const float* outf = g_outd[0] + (size_t)b * LL * HH;
        const float* outb = g_outd[1] + (size_t)b * LL * HH;
        for (int t = 0; t < LL; t++) {
            const float a = s_u[t];
            int t2 = len - 1 - t;
            if (t2 < 0) t2 = 0;
#pragma unroll
            for (int q = 0; q < 4; q++) {
                const int j = tid + q * 256;
                float hv;
                if (j < HH) hv = outf[(size_t)t * HH + j];
                else        hv = outb[(size_t)t2 * HH + (j - HH)];
                accj[q] = fmaf(a, hv, accj[q]);
            }
        }
#pragma unroll
        for (int q = 0; q < 4; q++) s_ctx[tid + q * 256] = accj[q];
    }
    __syncthreads();

    for (int i = 0; i < 64; i++) {
        const int o = warp * 64 + i;
        const float* wr = W_lin + (size_t)o * (2 * HH);
        float a = 0.f;
#pragma unroll 8
        for (int q = 0; q < 32; q++) {
            int d = lane + q * 32;
            a = fmaf(s_ctx[d], wr[d], a);
        }
#pragma unroll
        for (int off = 16; off; off >>= 1)
            a += __shfl_xor_sync(0xffffffffu, a, off);
        if (lane == 0) s_lin[o] = fmaxf(a + b_lin[o], 0.f);
    }
    __syncthreads();

    if (warp == 0) {
#pragma unroll
        for (int o = 0; o < 3; o++) {
            const float* wr = W_out + (size_t)o * 512;
            float a = 0.f;
#pragma unroll
            for (int q = 0; q < 16; q++) {
                int d = lane + q * 32;
                a = fmaf(s_lin[d], wr[d], a);
            }
#pragma unroll
            for (int off = 16; off; off >>= 1)
                a += __shfl_xor_sync(0xffffffffu, a, off);
            if (lane == 0) out[b * 3 + o] = a + b_out[o];
        }
    }
}

// ---------------- launch -----------------------------------------------------
extern "C" void kernel_launch(void* const* d_in, const int* in_sizes, int n_in,
                              void* d_out, int out_size)
{
    const float* x           = (const float*)d_in[0];
    const int*   x_len       = (const int*)d_in[1];
    const float* target_word = (const float*)d_in[3];
    const float* W_ih_f      = (const float*)d_in[5];
    const float* W_hh_f      = (const float*)d_in[6];
    const float* b_f         = (const float*)d_in[7];
    const float* W_ih_b      = (const float*)d_in[8];
    const float* W_hh_b      = (const float*)d_in[9];
    const float* b_b         = (const float*)d_in[10];
    const float* W_h         = (const float*)d_in[11];
    const float* b_tanh      = (const float*)d_in[12];
    const float* W_lin       = (const float*)d_in[13];
    const float* b_lin       = (const float*)d_in[14];
    const float* W_out       = (const float*)d_in[15];
    const float* b_out       = (const float*)d_in[16];
    float* out = (float*)d_out;

    static bool attr_set = false;
    if (!attr_set) {
        cudaFuncSetAttribute(lstm_mma_step,
                             cudaFuncAttributeMaxDynamicSharedMemorySize, R6_SMEM);
        attr_set = true;
    }

    init_hc_kernel<<<(BB * HH + 255) / 256, 256>>>();
    convert_x_kernel<<<BB * LL, 256>>>(x);
    convert_w_kernel<<<GNF, 256>>>(W_ih_f, W_ih_b, b_f, b_b);
    {
        dim3 wgrid(G4H, 2);
        convert_whh_kernel<<<wgrid, 128>>>(W_hh_f, W_hh_b);
    }

    dim3 ggrid(GNF / 128, MM_TOT / 128);   // (32, 256)
    gemm_mma_kernel<<<ggrid, 256>>>();

    dim3 sgrid(G4H / 128, BB / 64, 2);     // (16, 4, 2)
    for (int t = 0; t < LL; t++)
        lstm_mma_step<<<sgrid, 256, R6_SMEM>>>(x_len, t);

    final_kernel<<<BB, 256>>>(x, x_len, target_word, W_h, b_tanh,
                              W_lin, b_lin, W_out, b_out, out);
}

// round 7
// speedup vs baseline: 2.3845x; 1.0563x over previous
#include <cuda_runtime.h>
#include <cuda_bf16.h>
#include <math.h>
#include <stdint.h>

// Problem dims
#define BB 256
#define LL 128
#define DD 1024
#define HH 512
#define G4H 2048
#define GNF 4096
#define KS 3072
#define MM_TOT (LL * BB)
#define NBLK 128           // persistent grid size

// ---------------- scratch (device globals) ----------------------------------
__device__ float g_G[(size_t)MM_TOT * GNF];          // gate-interleaved cols
__device__ float g_outd[2][(size_t)BB * LL * HH];
__device__ float g_h[2][2][(size_t)BB * HH];
__device__ float g_c[2][2][(size_t)BB * HH];
__device__ __nv_bfloat16 g_hhi[2][2][(size_t)BB * HH];
__device__ __nv_bfloat16 g_hlo[2][2][(size_t)BB * HH];
__device__ __nv_bfloat16 g_Xs[(size_t)MM_TOT * KS];
__device__ __nv_bfloat16 g_Ws[(size_t)GNF * KS];
__device__ __nv_bfloat16 g_Whh[2][(size_t)G4H * 1024];
__device__ float g_bias[GNF];
__device__ unsigned int g_bar_cnt;
__device__ unsigned int g_bar_gen;

// ---------------- helpers ----------------------------------------------------
__device__ __forceinline__ uint32_t smem_u32(const void* p) {
    uint32_t a;
    asm("{ .reg .u64 t; cvta.to.shared.u64 t, %1; cvt.u32.u64 %0, t; }"
        : "=r"(a) : "l"(p));
    return a;
}
#define CPA16(dst, src) \
    asm volatile("cp.async.ca.shared.global [%0], [%1], 16;" :: "r"(dst), "l"(src))
#define CPA_COMMIT() asm volatile("cp.async.commit_group;" ::: "memory")

__device__ __forceinline__ void ldmatrix_x4(uint32_t* r, uint32_t addr) {
    asm volatile("ldmatrix.sync.aligned.m8n8.x4.shared.b16 {%0,%1,%2,%3}, [%4];"
                 : "=r"(r[0]), "=r"(r[1]), "=r"(r[2]), "=r"(r[3]) : "r"(addr));
}
__device__ __forceinline__ void mma16816(float* c, const uint32_t* a,
                                         uint32_t b0, uint32_t b1) {
    asm volatile(
        "mma.sync.aligned.m16n8k16.row.col.f32.bf16.bf16.f32 "
        "{%0,%1,%2,%3}, {%4,%5,%6,%7}, {%8,%9}, {%0,%1,%2,%3};"
        : "+f"(c[0]), "+f"(c[1]), "+f"(c[2]), "+f"(c[3])
        : "r"(a[0]), "r"(a[1]), "r"(a[2]), "r"(a[3]), "r"(b0), "r"(b1));
}
__device__ __forceinline__ float fsigmoid(float x) {
    return __fdividef(1.f, 1.f + __expf(-x));
}
__device__ __forceinline__ float ftanh(float x) {
    float e2 = __expf(2.f * x);
    return __fdividef(e2 - 1.f, e2 + 1.f);
}

// grid-wide barrier for co-resident persistent blocks
__device__ __forceinline__ void grid_barrier(int step) {
    __syncthreads();
    if (threadIdx.x == 0) {
        __threadfence();
        unsigned int a = atomicAdd(&g_bar_cnt, 1u);
        if (a == NBLK - 1) {
            g_bar_cnt = 0;
            __threadfence();
            atomicExch(&g_bar_gen, (unsigned)(step + 1));
        } else {
            unsigned int g;
            do {
                asm volatile("ld.acquire.gpu.u32 %0, [%1];"
                             : "=r"(g) : "l"(&g_bar_gen));
                if (g > (unsigned)step) break;
                __nanosleep(64);
            } while (true);
        }
    }
    __syncthreads();
}

// ---------------- init -------------------------------------------------------
__global__ void init_hc_kernel() {
    int i = blockIdx.x * blockDim.x + threadIdx.x;
    if (i == 0) { g_bar_cnt = 0; g_bar_gen = 0; }
    if (i < BB * HH) {
        g_h[0][0][i] = 0.f; g_h[1][0][i] = 0.f;
        g_c[0][0][i] = 0.f; g_c[1][0][i] = 0.f;
        g_hhi[0][0][i] = __float2bfloat16_rn(0.f);
        g_hhi[1][0][i] = __float2bfloat16_rn(0.f);
        g_hlo[0][0][i] = __float2bfloat16_rn(0.f);
        g_hlo[1][0][i] = __float2bfloat16_rn(0.f);
    }
}

// ---------------- fp32 -> bf16 hi/lo split converters ------------------------
__global__ __launch_bounds__(256)
void convert_x_kernel(const float* __restrict__ X) {
    const int bt = blockIdx.x;
    const int b = bt >> 7;
    const int t = bt & 127;
    const float4 v = ((const float4*)(X + (size_t)bt * DD))[threadIdx.x];
    __nv_bfloat16 hi4[4], lo4[4];
    hi4[0] = __float2bfloat16_rn(v.x); lo4[0] = __float2bfloat16_rn(v.x - __bfloat162float(hi4[0]));
    hi4[1] = __float2bfloat16_rn(v.y); lo4[1] = __float2bfloat16_rn(v.y - __bfloat162float(hi4[1]));
    hi4[2] = __float2bfloat16_rn(v.z); lo4[2] = __float2bfloat16_rn(v.z - __bfloat162float(hi4[2]));
    hi4[3] = __float2bfloat16_rn(v.w); lo4[3] = __float2bfloat16_rn(v.w - __bfloat162float(hi4[3]));
    const size_t base = ((size_t)t * BB + b) * KS + threadIdx.x * 4;
    *(uint2*)&g_Xs[base]        = *(const uint2*)hi4;
    *(uint2*)&g_Xs[base + DD]   = *(const uint2*)lo4;
    *(uint2*)&g_Xs[base + 2*DD] = *(const uint2*)hi4;
}

__global__ __launch_bounds__(256)
void convert_w_kernel(const float* __restrict__ Wf, const float* __restrict__ Wb,
                      const float* __restrict__ bf, const float* __restrict__ bb) {
    const int c = blockIdx.x;             // 0..4095 output row (gate-interleaved)
    const int dir = (c >= G4H);
    const int local = c - dir * G4H;
    const int j = local >> 2, gate = local & 3;
    const int srow = gate * HH + j;
    const float* src = dir ? (Wb + (size_t)srow * DD) : (Wf + (size_t)srow * DD);
    const float4 v = ((const float4*)src)[threadIdx.x];
    __nv_bfloat16 hi4[4], lo4[4];
    hi4[0] = __float2bfloat16_rn(v.x); lo4[0] = __float2bfloat16_rn(v.x - __bfloat162float(hi4[0]));
    hi4[1] = __float2bfloat16_rn(v.y); lo4[1] = __float2bfloat16_rn(v.y - __bfloat162float(hi4[1]));
    hi4[2] = __float2bfloat16_rn(v.z); lo4[2] = __float2bfloat16_rn(v.z - __bfloat162float(hi4[2]));
    hi4[3] = __float2bfloat16_rn(v.w); lo4[3] = __float2bfloat16_rn(v.w - __bfloat162float(hi4[3]));
    const size_t base = (size_t)c * KS + threadIdx.x * 4;
    *(uint2*)&g_Ws[base]        = *(const uint2*)hi4;
    *(uint2*)&g_Ws[base + DD]   = *(const uint2*)hi4;
    *(uint2*)&g_Ws[base + 2*DD] = *(const uint2*)lo4;
    if (threadIdx.x == 0)
        g_bias[c] = dir ? bb[srow] : bf[srow];
}

__global__ __launch_bounds__(128)
void convert_whh_kernel(const float* __restrict__ Wf, const float* __restrict__ Wb) {
    const int c   = blockIdx.x;
    const int dir = blockIdx.y;
    const int gate = c & 3, j = c >> 2;
    const float* __restrict__ W = dir ? Wb : Wf;
    const float4 v = ((const float4*)(W + (size_t)(gate * HH + j) * HH))[threadIdx.x];
    __nv_bfloat16 hi4[4], lo4[4];
    hi4[0] = __float2bfloat16_rn(v.x); lo4[0] = __float2bfloat16_rn(v.x - __bfloat162float(hi4[0]));
    hi4[1] = __float2bfloat16_rn(v.y); lo4[1] = __float2bfloat16_rn(v.y - __bfloat162float(hi4[1]));
    hi4[2] = __float2bfloat16_rn(v.z); lo4[2] = __float2bfloat16_rn(v.z - __bfloat162float(hi4[2]));
    hi4[3] = __float2bfloat16_rn(v.w); lo4[3] = __float2bfloat16_rn(v.w - __bfloat162float(hi4[3]));
    __nv_bfloat16* dst = &g_Whh[dir][(size_t)c * 1024];
    *(uint2*)&dst[threadIdx.x * 4]       = *(const uint2*)hi4;
    *(uint2*)&dst[512 + threadIdx.x * 4] = *(const uint2*)lo4;
}

// ---------------- mma.sync input-projection GEMM (validated) -----------------
#define NKT (KS / 32)
#define SROW 80
#define STILE (128 * SROW)

__global__ __launch_bounds__(256, 2)
void gemm_mma_kernel() {
    __shared__ __align__(16) char smA[2][STILE];
    __shared__ __align__(16) char smB[2][STILE];

    const int tid  = threadIdx.x;
    const int wid  = tid >> 5;
    const int lane = tid & 31;
    const int nTile = blockIdx.x * 128;
    const int mTile = blockIdx.y * 128;

    const int wm = wid & 3;
    const int wn = wid >> 2;
    const int m0 = wm * 32;
    const int n0 = wn * 64;

    const int lrow = tid >> 1;
    const int lk   = tid & 1;
    const __nv_bfloat16* __restrict__ gA =
        g_Xs + (size_t)(mTile + lrow) * KS + lk * 16;
    const __nv_bfloat16* __restrict__ gB =
        g_Ws + (size_t)(nTile + lrow) * KS + lk * 16;

    const uint32_t baseA = smem_u32(smA);
    const uint32_t baseB = smem_u32(smB);
    const uint32_t stDstA = baseA + lrow * SROW + lk * 32;
    const uint32_t stDstB = baseB + lrow * SROW + lk * 32;

    float acc[2][8][4];
#pragma unroll
    for (int i = 0; i < 2; i++)
#pragma unroll
        for (int j = 0; j < 8; j++)
#pragma unroll
            for (int q = 0; q < 4; q++) acc[i][j][q] = 0.f;

    const int r8 = lane & 7;
    const int tI = lane >> 3;
    const uint32_t aLaneOff = (uint32_t)((r8 + (tI & 1) * 8) * SROW + (tI >> 1) * 16);
    const uint32_t bLaneOff = (uint32_t)((r8 + (tI >> 1) * 8) * SROW + (tI & 1) * 16);

    CPA16(stDstA, gA);        CPA16(stDstA + 16, gA + 8);
    CPA16(stDstB, gB);        CPA16(stDstB + 16, gB + 8);
    CPA_COMMIT();

    int buf = 0;
    for (int kt = 0; kt < NKT; kt++) {
        if (kt < NKT - 1) {
            const __nv_bfloat16* pa = gA + (size_t)(kt + 1) * 32;
            const __nv_bfloat16* pb = gB + (size_t)(kt + 1) * 32;
            const uint32_t dA = stDstA + (buf ^ 1) * STILE;
            const uint32_t dB = stDstB + (buf ^ 1) * STILE;
            CPA16(dA, pa); CPA16(dA + 16, pa + 8);
            CPA16(dB, pb); CPA16(dB + 16, pb + 8);
            CPA_COMMIT();
            asm volatile("cp.async.wait_group 1;" ::: "memory");
        } else {
            asm volatile("cp.async.wait_group 0;" ::: "memory");
        }
        __syncthreads();

        const uint32_t abuf = baseA + buf * STILE;
        const uint32_t bbuf = baseB + buf * STILE;
#pragma unroll
        for (int kk = 0; kk < 2; kk++) {
            uint32_t afr[2][4], bfr[4][4];
#pragma unroll
            for (int mi = 0; mi < 2; mi++)
                ldmatrix_x4(afr[mi],
                            abuf + (uint32_t)((m0 + mi * 16) * SROW + kk * 32) + aLaneOff);
#pragma unroll
            for (int nb = 0; nb < 4; nb++)
                ldmatrix_x4(bfr[nb],
                            bbuf + (uint32_t)((n0 + nb * 16) * SROW + kk * 32) + bLaneOff);
#pragma unroll
            for (int mi = 0; mi < 2; mi++)
#pragma unroll
                for (int ni = 0; ni < 8; ni++) {
                    const uint32_t* bp = &bfr[ni >> 1][(ni & 1) * 2];
                    mma16816(acc[mi][ni], afr[mi], bp[0], bp[1]);
                }
        }
        __syncthreads();
        buf ^= 1;
    }

    const int gid = lane >> 2;
    const int tig = lane & 3;
#pragma unroll
    for (int mi = 0; mi < 2; mi++) {
        const int m = mTile + m0 + mi * 16 + gid;
#pragma unroll
        for (int ni = 0; ni < 8; ni++) {
            const int n = nTile + n0 + ni * 8 + tig * 2;
            const float2 bv = *(const float2*)&g_bias[n];
            float2 o0 = make_float2(acc[mi][ni][0] + bv.x, acc[mi][ni][1] + bv.y);
            float2 o1 = make_float2(acc[mi][ni][2] + bv.x, acc[mi][ni][3] + bv.y);
            *(float2*)&g_G[(size_t)m * GNF + n]       = o0;
            *(float2*)&g_G[(size_t)(m + 8) * GNF + n] = o1;
        }
    }
}

// ---------------- persistent tensor-core recurrence --------------------------
#define SROW2 144
#define A2_TILE (64 * SROW2)      // 9216
#define B2_TILE (128 * SROW2)     // 18432
#define STG     (A2_TILE + B2_TILE)
#define R6_SMEM (3 * STG)         // 82944
#define RKT2 24

__global__ __launch_bounds__(256)
void lstm_persistent(const int* __restrict__ x_len)
{
    extern __shared__ __align__(16) char sm[];
    const uint32_t sbase = smem_u32(sm);
    float* __restrict__ sR = (float*)sm;

    const int tid  = threadIdx.x;
    const int wid  = tid >> 5;
    const int lane = tid & 31;
    const int nTile = blockIdx.x * 128;
    const int b0    = blockIdx.y * 64;
    const int dir   = blockIdx.z;

    const __nv_bfloat16* __restrict__ Wd = g_Whh[dir];
    float* __restrict__ outp = g_outd[dir];

    // load mappings (step-invariant)
    const int aRow0 = tid >> 3;
    const int aRow1 = (tid + 256) >> 3;
    const int aCol  = (tid & 7) * 8;
    const uint32_t dA_off0 = (uint32_t)(aRow0 * SROW2 + (tid & 7) * 16);
    const uint32_t dA_off1 = (uint32_t)(aRow1 * SROW2 + (tid & 7) * 16);

    // warp tiling (step-invariant)
    const int m0 = (wid & 1) * 32;
    const int n0 = (wid >> 1) * 32;
    const int r8 = lane & 7;
    const int tI = lane >> 3;
    const uint32_t aLaneOff = (uint32_t)((r8 + (tI & 1) * 8) * SROW2 + (tI >> 1) * 16);
    const uint32_t bLaneOff = (uint32_t)((r8 + (tI >> 1) * 8) * SROW2 + (tI & 1) * 16);
    const int gid = lane >> 2;
    const int tig = lane & 3;
    const int jBase = nTile >> 2;

    for (int t = 0; t < LL; t++) {
        const int p = t & 1;
        const __nv_bfloat16* __restrict__ hhi = g_hhi[dir][p];
        const __nv_bfloat16* __restrict__ hlo = g_hlo[dir][p];
        const float* __restrict__ hprev = g_h[dir][p];
        const float* __restrict__ cprev = g_c[dir][p];
        float* __restrict__ hnext = g_h[dir][p ^ 1];
        float* __restrict__ cnext = g_c[dir][p ^ 1];
        __nv_bfloat16* __restrict__ hhin = g_hhi[dir][p ^ 1];
        __nv_bfloat16* __restrict__ hlon = g_hlo[dir][p ^ 1];

        auto issue_stage = [&](int kt, int stage) {
            const int seg  = kt >> 3;
            const int acol = (kt & 7) * 64;
            const int bcol = (seg == 2) ? (512 + (kt & 7) * 64) : ((kt & 7) * 64);
            const __nv_bfloat16* __restrict__ hsrc = (seg == 1) ? hlo : hhi;
            const uint32_t sa = sbase + stage * STG;
            const uint32_t sb = sa + A2_TILE;
            CPA16(sa + dA_off0, hsrc + (size_t)(b0 + aRow0) * HH + acol + aCol);
            CPA16(sa + dA_off1, hsrc + (size_t)(b0 + aRow1) * HH + acol + aCol);
#pragma unroll
            for (int q = 0; q < 4; q++) {
                const int chunk = tid + q * 256;
                const int br = chunk >> 3;
                const int bc = (chunk & 7) * 8;
                CPA16(sb + (uint32_t)(br * SROW2 + (chunk & 7) * 16),
                      Wd + (size_t)(nTile + br) * 1024 + bcol + bc);
            }
        };

        float acc[2][4][4];
#pragma unroll
        for (int i = 0; i < 2; i++)
#pragma unroll
            for (int j = 0; j < 4; j++)
#pragma unroll
                for (int q = 0; q < 4; q++) acc[i][j][q] = 0.f;

        issue_stage(0, 0); CPA_COMMIT();
        issue_stage(1, 1); CPA_COMMIT();

        for (int kt = 0; kt < RKT2; kt++) {
            if (kt + 2 < RKT2) issue_stage(kt + 2, (kt + 2) % 3);
            CPA_COMMIT();
            asm volatile("cp.async.wait_group 2;" ::: "memory");
            __syncthreads();

            const uint32_t sa = sbase + (kt % 3) * STG;
            const uint32_t sb = sa + A2_TILE;
#pragma unroll
            for (int kk = 0; kk < 4; kk++) {
                uint32_t afr[2][4], bfr[2][4];
#pragma unroll
                for (int mi = 0; mi < 2; mi++)
                    ldmatrix_x4(afr[mi],
                                sa + (uint32_t)((m0 + mi * 16) * SROW2 + kk * 32) + aLaneOff);
#pragma unroll
                for (int nb = 0; nb < 2; nb++)
                    ldmatrix_x4(bfr[nb],
                                sb + (uint32_t)((n0 + nb * 16) * SROW2 + kk * 32) + bLaneOff);
#pragma unroll
                for (int mi = 0; mi < 2; mi++)
#pragma unroll
                    for (int ni = 0; ni < 4; ni++) {
                        const uint32_t* bp = &bfr[ni >> 1][(ni & 1) * 2];
                        mma16816(acc[mi][ni], afr[mi], bp[0], bp[1]);
                    }
            }
            __syncthreads();
        }

        // stage R through smem
#pragma unroll
        for (int mi = 0; mi < 2; mi++) {
            const int row = m0 + mi * 16 + gid;
#pragma unroll
            for (int ni = 0; ni < 4; ni++) {
                const int col = n0 + ni * 8 + tig * 2;
                sR[row * 132 + col]           = acc[mi][ni][0];
                sR[row * 132 + col + 1]       = acc[mi][ni][1];
                sR[(row + 8) * 132 + col]     = acc[mi][ni][2];
                sR[(row + 8) * 132 + col + 1] = acc[mi][ni][3];
            }
        }
        __syncthreads();

        // fused LSTM pointwise
#pragma unroll
        for (int it = 0; it < 8; it++) {
            const int idx = it * 256 + tid;
            const int bl = idx >> 5;
            const int jj = idx & 31;
            const int b  = b0 + bl;
            const int j  = jBase + jj;
            const int len = x_len[b];
            int tq = t;
            if (dir) { tq = len - 1 - t; if (tq < 0) tq = 0; }
            const float4 gp = *(const float4*)(
                g_G + ((size_t)tq * BB + b) * GNF + dir * G4H + (size_t)j * 4);
            const float4 rv = *(const float4*)&sR[bl * 132 + jj * 4];
            float i_ = fsigmoid(rv.x + gp.x);
            float f_ = fsigmoid(rv.y + gp.y);
            float g_ = ftanh(rv.z + gp.z);
            float o_ = fsigmoid(rv.w + gp.w);
            const size_t hc = (size_t)b * HH + j;
            float cp = cprev[hc];
            float hp = hprev[hc];
            float cn = f_ * cp + i_ * g_;
            float hn = o_ * ftanh(cn);
            const bool valid = (t < len);
            const float ho = valid ? hn : hp;
            const float co = valid ? cn : cp;
            hnext[hc] = ho;
            cnext[hc] = co;
            __nv_bfloat16 hi = __float2bfloat16_rn(ho);
            hhin[hc] = hi;
            hlon[hc] = __float2bfloat16_rn(ho - __bfloat162float(hi));
            outp[((size_t)b * LL + t) * HH + j] = valid ? hn : 0.f;
        }

        grid_barrier(t);
    }
}

// ---------------- attention + head (one block per batch) ---------------------
__global__ __launch_bounds__(256)
void final_kernel(const float* __restrict__ x, const int* __restrict__ x_len,
                  const float* __restrict__ target_word,
                  const float* __restrict__ W_h, const float* __restrict__ b_tanh,
                  const float* __restrict__ W_lin, const float* __restrict__ b_lin,
                  const float* __restrict__ W_out, const float* __restrict__ b_out,
                  float* __restrict__ out)
{
    __shared__ float s_u[LL];
    __shared__ float s_ctx[2 * HH];
    __shared__ float s_lin[512];
    __shared__ float s_red[8];
    __shared__ float s_twdot;

    const int b    = blockIdx.x;
    const int tid  = threadIdx.x;
    const int warp = tid >> 5;
    const int lane = tid & 31;
    const int len  = x_len[b];

    {
        float partial = 0.f;
        for (int d = tid; d < DD; d += 256) {
            float s = 0.f;
#pragma unroll
            for (int k = 0; k < 5; k++)
                s += target_word[((size_t)b * 5 + k) * DD + d];
            partial = fmaf(s * 0.2f, W_h[DD + d], partial);
        }
#pragma unroll
        for (int off = 16; off; off >>= 1)
            partial += __shfl_xor_sync(0xffffffffu, partial, off);
        if (lane == 0) s_red[warp] = partial;
        __syncthreads();
        if (tid == 0) {
            float s = 0.f;
            for (int w = 0; w < 8; w++) s += s_red[w];
            s_twdot = s;
        }
        __syncthreads();
    }
    const float twdot = s_twdot;

    for (int i = 0; i < 16; i++) {
        const int t = warp * 16 + i;
        const float* xe = x + ((size_t)b * LL + t) * DD;
        float a = 0.f;
#pragma unroll 8
        for (int q = 0; q < 32; q++) {
            int d = lane + q * 32;
            a = fmaf(xe[d], W_h[d], a);
        }
#pragma unroll
        for (int off = 16; off; off >>= 1)
            a += __shfl_xor_sync(0xffffffffu, a, off);
        if (lane == 0)
            s_u[t] = (t < len) ? (a + twdot + b_tanh[t]) : -1e6f;
    }
    __syncthreads();

    if (warp == 0) {
        float v[4];
#pragma unroll
        for (int q = 0; q < 4; q++) v[q] = s_u[lane + q * 32];
        float m = fmaxf(fmaxf(v[0], v[1]), fmaxf(v[2], v[3]));
#pragma unroll
        for (int off = 16; off; off >>= 1)
            m = fmaxf(m, __shfl_xor_sync(0xffffffffu, m, off));
        float e[4], s = 0.f;
#pragma unroll
        for (int q = 0; q < 4; q++) { e[q] = expf(v[q] - m); s += e[q]; }
#pragma unroll
        for (int off = 16; off; off >>= 1)
            s += __shfl_xor_sync(0xffffffffu, s, off);
        float inv = 1.f / s;
#pragma unroll
        for (int q = 0; q < 4; q++) s_u[lane + q * 32] = e[q] * inv;
    }
    __syncthreads();

    {
        float accj[4] = {0.f, 0.f, 0.f, 0.f};
        const float* outf = g_outd[0] + (size_t)b * LL * HH;
        const float* outb = g_outd[1] + (size_t)b * LL * HH;
        for (int t = 0; t < LL; t++) {
            const float a = s_u[t];
            int t2 = len - 1 - t;
            if (t2 < 0) t2 = 0;
#pragma unroll
            for (int q = 0; q < 4; q++) {
                const int j = tid + q * 256;
                float hv;
                if (j < HH) hv = outf[(size_t)t * HH + j];
                else        hv = outb[(size_t)t2 * HH + (j - HH)];
                accj[q] = fmaf(a, hv, accj[q]);
            }
        }
#pragma unroll
        for (int q = 0; q < 4; q++) s_ctx[tid + q * 256] = accj[q];
    }
    __syncthreads();

    for (int i = 0; i < 64; i++) {
        const int o = warp * 64 + i;
        const float* wr = W_lin + (size_t)o * (2 * HH);
        float a = 0.f;
#pragma unroll 8
        for (int q = 0; q < 32; q++) {
            int d = lane + q * 32;
            a = fmaf(s_ctx[d], wr[d], a);
        }
#pragma unroll
        for (int off = 16; off; off >>= 1)
            a += __shfl_xor_sync(0xffffffffu, a, off);
        if (lane == 0) s_lin[o] = fmaxf(a + b_lin[o], 0.f);
    }
    __syncthreads();

    if (warp == 0) {
#pragma unroll
        for (int o = 0; o < 3; o++) {
            const float* wr = W_out + (size_t)o * 512;
            float a = 0.f;
#pragma unroll
            for (int q = 0; q < 16; q++) {
                int d = lane + q * 32;
                a = fmaf(s_lin[d], wr[d], a);
            }
#pragma unroll
            for (int off = 16; off; off >>= 1)
                a += __shfl_xor_sync(0xffffffffu, a, off);
            if (lane == 0) out[b * 3 + o] = a + b_out[o];
        }
    }
}

// ---------------- launch -----------------------------------------------------
extern "C" void kernel_launch(void* const* d_in, const int* in_sizes, int n_in,
                              void* d_out, int out_size)
{
    const float* x           = (const float*)d_in[0];
    const int*   x_len       = (const int*)d_in[1];
    const float* target_word = (const float*)d_in[3];
    const float* W_ih_f      = (const float*)d_in[5];
    const float* W_hh_f      = (const float*)d_in[6];
    const float* b_f         = (const float*)d_in[7];
    const float* W_ih_b      = (const float*)d_in[8];
    const float* W_hh_b      = (const float*)d_in[9];
    const float* b_b         = (const float*)d_in[10];
    const float* W_h         = (const float*)d_in[11];
    const float* b_tanh      = (const float*)d_in[12];
    const float* W_lin       = (const float*)d_in[13];
    const float* b_lin       = (const float*)d_in[14];
    const float* W_out       = (const float*)d_in[15];
    const float* b_out       = (const float*)d_in[16];
    float* out = (float*)d_out;

    static bool attr_set = false;
    if (!attr_set) {
        cudaFuncSetAttribute(lstm_persistent,
                             cudaFuncAttributeMaxDynamicSharedMemorySize, R6_SMEM);
        attr_set = true;
    }

    init_hc_kernel<<<(BB * HH + 255) / 256, 256>>>();
    convert_x_kernel<<<BB * LL, 256>>>(x);
    convert_w_kernel<<<GNF, 256>>>(W_ih_f, W_ih_b, b_f, b_b);
    {
        dim3 wgrid(G4H, 2);
        convert_whh_kernel<<<wgrid, 128>>>(W_hh_f, W_hh_b);
    }

    dim3 ggrid(GNF / 128, MM_TOT / 128);   // (32, 256)
    gemm_mma_kernel<<<ggrid, 256>>>();

    dim3 sgrid(G4H / 128, BB / 64, 2);     // (16, 4, 2) = 128 persistent blocks
    lstm_persistent<<<sgrid, 256, R6_SMEM>>>(x_len);

    final_kernel<<<BB, 256>>>(x, x_len, target_word, W_h, b_tanh,
                              W_lin, b_lin, W_out, b_out, out);
}